// round 2
// baseline (speedup 1.0000x reference)
#include <cuda_runtime.h>
#include <math.h>

// Problem constants
#define T_TOK   4096
#define D_IN    768
#define NEXP    8
#define H_DIM   3072
#define O_DIM   768
#define OUT_ELEMS  (T_TOK * O_DIM)     // 3145728 floats (main output)
#define GATE_ELEMS (T_TOK * NEXP)      // 32768 floats (gate_weights output)
#define ROWCAP  8320                   // 2*T rows + tile padding slack

// GEMM tiling
#define BM 128
#define BN 64
#define BK 32
#define AT_STRIDE 132                  // padded (multiple of 4 -> 16B aligned vec4 rows)

// ---------------- scratch (__device__ globals; no allocations) ----------------
__device__ int   g_cnt[NEXP];
__device__ int   g_off[NEXP];
__device__ int   g_cursor[NEXP];
__device__ int   g_tope[T_TOK * 2];
__device__ float g_topw[T_TOK * 2];
__device__ int   g_rowtok[ROWCAP];
__device__ float g_roww[ROWCAP];
__device__ float g_h[(size_t)ROWCAP * H_DIM];   // ~102 MB hidden scratch

// ---------------- helpers ----------------
__device__ __forceinline__ float gelu_exact(float v) {
    return 0.5f * v * (1.0f + erff(v * 0.70710678118654752f));
}

// ---------------- kernel 0: zero output + counts ----------------
__global__ void zero_kernel(float* __restrict__ out) {
    int idx = blockIdx.x * blockDim.x + threadIdx.x;
    float4 z = make_float4(0.f, 0.f, 0.f, 0.f);
    float4* o4 = reinterpret_cast<float4*>(out);
    const int n4 = OUT_ELEMS / 4;
    for (int i = idx; i < n4; i += gridDim.x * blockDim.x) o4[i] = z;
    if (idx < NEXP) g_cnt[idx] = 0;
}

// ---------------- kernel 1: gate (logits -> top2 -> softmax) ----------------
// One warp per token. Wg cached in smem. All-lane shfl reduce.
__global__ __launch_bounds__(256) void gate_kernel(
    const float* __restrict__ x, const float* __restrict__ Wg,
    float* __restrict__ gate_out, int write_gate)
{
    __shared__ float sWg[D_IN * NEXP];
    for (int i = threadIdx.x; i < D_IN * NEXP; i += blockDim.x) sWg[i] = Wg[i];
    __syncthreads();

    int warp = threadIdx.x >> 5, lane = threadIdx.x & 31;
    int t = blockIdx.x * 8 + warp;
    const float* xr = x + (size_t)t * D_IN;

    float acc[NEXP];
#pragma unroll
    for (int e = 0; e < NEXP; e++) acc[e] = 0.f;

    for (int d = lane; d < D_IN; d += 32) {
        float xv = xr[d];
#pragma unroll
        for (int e = 0; e < NEXP; e++) acc[e] = fmaf(xv, sWg[d * NEXP + e], acc[e]);
    }
#pragma unroll
    for (int o = 16; o > 0; o >>= 1)
#pragma unroll
        for (int e = 0; e < NEXP; e++) acc[e] += __shfl_xor_sync(0xffffffffu, acc[e], o);

    // top-2 (first-occurrence max semantics, matching lax.top_k)
    int i0 = 0; float v0 = acc[0];
#pragma unroll
    for (int e = 1; e < NEXP; e++) if (acc[e] > v0) { v0 = acc[e]; i0 = e; }
    int i1 = -1; float v1 = -3.4e38f;
#pragma unroll
    for (int e = 0; e < NEXP; e++) if (e != i0 && acc[e] > v1) { v1 = acc[e]; i1 = e; }

    float ew = expf(v1 - v0);
    float denom = 1.f + ew;
    float w0 = 1.f / denom;
    float w1 = ew / denom;

    if (write_gate && lane < NEXP)
        gate_out[t * NEXP + lane] = (lane == i0) ? w0 : ((lane == i1) ? w1 : 0.f);

    if (lane == 0) {
        g_tope[2 * t]     = i0; g_topw[2 * t]     = w0;
        g_tope[2 * t + 1] = i1; g_topw[2 * t + 1] = w1;
        atomicAdd(&g_cnt[i0], 1);
        atomicAdd(&g_cnt[i1], 1);
    }
}

// ---------------- kernel 2: tiny exclusive scan ----------------
__global__ void scan_kernel() {
    if (threadIdx.x == 0) {
        int off = 0;
        for (int e = 0; e < NEXP; e++) {
            g_off[e] = off; g_cursor[e] = off; off += g_cnt[e];
        }
    }
}

// ---------------- kernel 3: scatter tokens into per-expert compact lists ----
__global__ void scatter_kernel() {
    int t = blockIdx.x * blockDim.x + threadIdx.x;
    if (t >= T_TOK) return;
#pragma unroll
    for (int k = 0; k < 2; k++) {
        int e = g_tope[2 * t + k];
        float w = g_topw[2 * t + k];
        int pos = atomicAdd(&g_cursor[e], 1);
        g_rowtok[pos] = t;
        g_roww[pos] = w;
    }
}

// ---------------- kernel 4: FFN1  h = gelu(x @ W1[e] + b1[e]) --------------
// 128x64x32 tile, 8x4 micro-tile, A gathered by token id, K-transposed smem A.
__global__ __launch_bounds__(256) void ffn1_kernel(
    const float* __restrict__ x, const float* __restrict__ W1,
    const float* __restrict__ b1)
{
    const int e = blockIdx.z;
    const int cnt = g_cnt[e];
    const int rt = blockIdx.y;
    if (rt * BM >= cnt) return;
    const int m0 = g_off[e] + rt * BM;
    const int n0 = blockIdx.x * BN;

    __shared__ alignas(16) float sAT[BK * AT_STRIDE];   // [k][row], padded
    __shared__ alignas(16) float sB[BK][BN];
    __shared__ int stok[BM];

    const int tid = threadIdx.x;
    const int tx = tid & 15;        // col group (4 cols)
    const int ty = tid >> 4;        // row group (8 rows)

    if (tid < BM) {
        int slot = rt * BM + tid;
        stok[tid] = (slot < cnt) ? g_rowtok[m0 + tid] : g_rowtok[m0];
    }
    __syncthreads();

    const float* Wbase = W1 + (size_t)e * D_IN * H_DIM;
    float acc[8][4];
#pragma unroll
    for (int i = 0; i < 8; i++)
#pragma unroll
        for (int j = 0; j < 4; j++) acc[i][j] = 0.f;

    for (int k0 = 0; k0 < D_IN; k0 += BK) {
        // Load A tile: 128 rows x 32 k = 1024 float4, 4 per thread, transpose into sAT
#pragma unroll
        for (int li = 0; li < 4; li++) {
            int idx = tid + li * 256;          // 0..1023
            int row = idx >> 3;                // 0..127
            int kq  = (idx & 7) << 2;          // 0,4,...,28
            float4 v = *reinterpret_cast<const float4*>(
                x + (size_t)stok[row] * D_IN + k0 + kq);
            sAT[(kq + 0) * AT_STRIDE + row] = v.x;
            sAT[(kq + 1) * AT_STRIDE + row] = v.y;
            sAT[(kq + 2) * AT_STRIDE + row] = v.z;
            sAT[(kq + 3) * AT_STRIDE + row] = v.w;
        }
        // Load B tile: 32 k x 64 n = 512 float4, 2 per thread
#pragma unroll
        for (int li = 0; li < 2; li++) {
            int idx = tid + li * 256;          // 0..511
            int kr = idx >> 4;                 // 0..31
            int nq = (idx & 15) << 2;          // 0..60
            *reinterpret_cast<float4*>(&sB[kr][nq]) =
                *reinterpret_cast<const float4*>(
                    Wbase + (size_t)(k0 + kr) * H_DIM + n0 + nq);
        }
        __syncthreads();

#pragma unroll
        for (int kk = 0; kk < BK; kk++) {
            float4 a0 = *reinterpret_cast<const float4*>(&sAT[kk * AT_STRIDE + ty * 8]);
            float4 a1 = *reinterpret_cast<const float4*>(&sAT[kk * AT_STRIDE + ty * 8 + 4]);
            float4 b  = *reinterpret_cast<const float4*>(&sB[kk][tx * 4]);
            float a[8] = {a0.x, a0.y, a0.z, a0.w, a1.x, a1.y, a1.z, a1.w};
#pragma unroll
            for (int i = 0; i < 8; i++) {
                acc[i][0] = fmaf(a[i], b.x, acc[i][0]);
                acc[i][1] = fmaf(a[i], b.y, acc[i][1]);
                acc[i][2] = fmaf(a[i], b.z, acc[i][2]);
                acc[i][3] = fmaf(a[i], b.w, acc[i][3]);
            }
        }
        __syncthreads();
    }

    const float* bb = b1 + e * H_DIM + n0;
    float4 bv = *reinterpret_cast<const float4*>(&bb[tx * 4]);
#pragma unroll
    for (int i = 0; i < 8; i++) {
        int slot = rt * BM + ty * 8 + i;
        if (slot >= cnt) continue;
        int gr = m0 + ty * 8 + i;
        float4 r;
        r.x = gelu_exact(acc[i][0] + bv.x);
        r.y = gelu_exact(acc[i][1] + bv.y);
        r.z = gelu_exact(acc[i][2] + bv.z);
        r.w = gelu_exact(acc[i][3] + bv.w);
        *reinterpret_cast<float4*>(&g_h[(size_t)gr * H_DIM + n0 + tx * 4]) = r;
    }
}

// ---------------- kernel 5: FFN2  out[t] += w * (h @ W2[e] + b2[e]) --------
__global__ __launch_bounds__(256) void ffn2_kernel(
    const float* __restrict__ W2, const float* __restrict__ b2,
    float* __restrict__ out)
{
    const int e = blockIdx.z;
    const int cnt = g_cnt[e];
    const int rt = blockIdx.y;
    if (rt * BM >= cnt) return;
    const int m0 = g_off[e] + rt * BM;
    const int n0 = blockIdx.x * BN;

    __shared__ alignas(16) float sAT[BK * AT_STRIDE];
    __shared__ alignas(16) float sB[BK][BN];
    __shared__ int   stok[BM];
    __shared__ float sw[BM];

    const int tid = threadIdx.x;
    const int tx = tid & 15;
    const int ty = tid >> 4;

    if (tid < BM) {
        int slot = rt * BM + tid;
        stok[tid] = (slot < cnt) ? g_rowtok[m0 + tid] : 0;
        sw[tid]   = (slot < cnt) ? g_roww[m0 + tid]  : 0.f;
    }
    __syncthreads();

    const float* Wbase = W2 + (size_t)e * H_DIM * O_DIM;
    float acc[8][4];
#pragma unroll
    for (int i = 0; i < 8; i++)
#pragma unroll
        for (int j = 0; j < 4; j++) acc[i][j] = 0.f;

    for (int k0 = 0; k0 < H_DIM; k0 += BK) {
#pragma unroll
        for (int li = 0; li < 4; li++) {
            int idx = tid + li * 256;
            int row = idx >> 3;
            int kq  = (idx & 7) << 2;
            float4 v = *reinterpret_cast<const float4*>(
                &g_h[(size_t)(m0 + row) * H_DIM + k0 + kq]);
            sAT[(kq + 0) * AT_STRIDE + row] = v.x;
            sAT[(kq + 1) * AT_STRIDE + row] = v.y;
            sAT[(kq + 2) * AT_STRIDE + row] = v.z;
            sAT[(kq + 3) * AT_STRIDE + row] = v.w;
        }
#pragma unroll
        for (int li = 0; li < 2; li++) {
            int idx = tid + li * 256;
            int kr = idx >> 4;
            int nq = (idx & 15) << 2;
            *reinterpret_cast<float4*>(&sB[kr][nq]) =
                *reinterpret_cast<const float4*>(
                    Wbase + (size_t)(k0 + kr) * O_DIM + n0 + nq);
        }
        __syncthreads();

#pragma unroll
        for (int kk = 0; kk < BK; kk++) {
            float4 a0 = *reinterpret_cast<const float4*>(&sAT[kk * AT_STRIDE + ty * 8]);
            float4 a1 = *reinterpret_cast<const float4*>(&sAT[kk * AT_STRIDE + ty * 8 + 4]);
            float4 b  = *reinterpret_cast<const float4*>(&sB[kk][tx * 4]);
            float a[8] = {a0.x, a0.y, a0.z, a0.w, a1.x, a1.y, a1.z, a1.w};
#pragma unroll
            for (int i = 0; i < 8; i++) {
                acc[i][0] = fmaf(a[i], b.x, acc[i][0]);
                acc[i][1] = fmaf(a[i], b.y, acc[i][1]);
                acc[i][2] = fmaf(a[i], b.z, acc[i][2]);
                acc[i][3] = fmaf(a[i], b.w, acc[i][3]);
            }
        }
        __syncthreads();
    }

    const float* bb = b2 + e * O_DIM + n0;
    float4 bv = *reinterpret_cast<const float4*>(&bb[tx * 4]);
#pragma unroll
    for (int i = 0; i < 8; i++) {
        int slot = rt * BM + ty * 8 + i;
        if (slot >= cnt) continue;
        int t = stok[ty * 8 + i];
        float w = sw[ty * 8 + i];
        float* orow = out + (size_t)t * O_DIM + n0;
        atomicAdd(&orow[tx * 4 + 0], w * (acc[i][0] + bv.x));
        atomicAdd(&orow[tx * 4 + 1], w * (acc[i][1] + bv.y));
        atomicAdd(&orow[tx * 4 + 2], w * (acc[i][2] + bv.z));
        atomicAdd(&orow[tx * 4 + 3], w * (acc[i][3] + bv.w));
    }
}

// ---------------- launch ----------------
extern "C" void kernel_launch(void* const* d_in, const int* in_sizes, int n_in,
                              void* d_out, int out_size) {
    const float* x  = (const float*)d_in[0];
    const float* Wg = (const float*)d_in[1];
    const float* W1 = (const float*)d_in[2];
    const float* b1 = (const float*)d_in[3];
    const float* W2 = (const float*)d_in[4];
    const float* b2 = (const float*)d_in[5];
    float* out = (float*)d_out;
    int write_gate = (out_size >= OUT_ELEMS + GATE_ELEMS) ? 1 : 0;

    zero_kernel<<<1024, 256>>>(out);
    gate_kernel<<<T_TOK / 8, 256>>>(x, Wg, out + OUT_ELEMS, write_gate);
    scan_kernel<<<1, 32>>>();
    scatter_kernel<<<T_TOK / 256, 256>>>();
    // max rows per expert = T_TOK -> 32 tiles of 128 rows
    ffn1_kernel<<<dim3(H_DIM / BN, 32, NEXP), 256>>>(x, W1, b1);
    ffn2_kernel<<<dim3(O_DIM / BN, 32, NEXP), 256>>>(W2, b2, out);
}

// round 10
// speedup vs baseline: 1.7886x; 1.7886x over previous
#include <cuda_runtime.h>
#include <cuda_bf16.h>
#include <math.h>
#include <stdint.h>

// Problem constants
#define T_TOK   4096
#define D_IN    768
#define NEXP    8
#define H_DIM   3072
#define O_DIM   768
#define OUT_ELEMS  (T_TOK * O_DIM)
#define GATE_ELEMS (T_TOK * NEXP)
#define ROWCAP  8320

// GEMM tiling (mma.sync bf16 m16n8k16)
#define BM 128
#define BN 128
#define BK 32
#define ROWB 80               // bytes per smem row (64 data + 16 pad)
// smem byte offsets
#define A_HI 0
#define A_LO (BM * ROWB)
#define B_HI (2 * BM * ROWB)
#define B_LO (2 * BM * ROWB + BN * ROWB)
#define SMEM_TILE_BYTES (2 * BM * ROWB + 2 * BN * ROWB)  // 40960

// ---------------- scratch ----------------
__device__ int   g_cnt[NEXP];
__device__ int   g_off[NEXP];
__device__ int   g_cursor[NEXP];
__device__ int   g_tope[T_TOK * 2];
__device__ float g_topw[T_TOK * 2];
__device__ int   g_rowtok[ROWCAP];
__device__ float g_roww[ROWCAP];

__device__ __nv_bfloat16 g_xhi[T_TOK * D_IN];
__device__ __nv_bfloat16 g_xlo[T_TOK * D_IN];
__device__ __nv_bfloat16 g_w1hi[NEXP * H_DIM * D_IN];   // [e][n][k]
__device__ __nv_bfloat16 g_w1lo[NEXP * H_DIM * D_IN];
__device__ __nv_bfloat16 g_w2hi[NEXP * O_DIM * H_DIM];  // [e][n][k]
__device__ __nv_bfloat16 g_w2lo[NEXP * O_DIM * H_DIM];
__device__ __nv_bfloat16 g_hhi[(size_t)ROWCAP * H_DIM];
__device__ __nv_bfloat16 g_hlo[(size_t)ROWCAP * H_DIM];

// ---------------- helpers ----------------
__device__ __forceinline__ float gelu_exact(float v) {
    return 0.5f * v * (1.0f + erff(v * 0.70710678118654752f));
}
__device__ __forceinline__ void split_bf16(float v, __nv_bfloat16& hi, __nv_bfloat16& lo) {
    hi = __float2bfloat16(v);
    lo = __float2bfloat16(v - __bfloat162float(hi));
}
__device__ __forceinline__ void mma_bf16(float* c, const uint32_t* a,
                                         uint32_t b0, uint32_t b1) {
    asm volatile(
        "mma.sync.aligned.m16n8k16.row.col.f32.bf16.bf16.f32 "
        "{%0,%1,%2,%3}, {%4,%5,%6,%7}, {%8,%9}, {%0,%1,%2,%3};"
        : "+f"(c[0]), "+f"(c[1]), "+f"(c[2]), "+f"(c[3])
        : "r"(a[0]), "r"(a[1]), "r"(a[2]), "r"(a[3]), "r"(b0), "r"(b1));
}

// ---------------- kernel: zero output + counts ----------------
__global__ void zero_kernel(float* __restrict__ out) {
    int idx = blockIdx.x * blockDim.x + threadIdx.x;
    float4 z = make_float4(0.f, 0.f, 0.f, 0.f);
    float4* o4 = reinterpret_cast<float4*>(out);
    const int n4 = OUT_ELEMS / 4;
    for (int i = idx; i < n4; i += gridDim.x * blockDim.x) o4[i] = z;
    if (idx < NEXP) g_cnt[idx] = 0;
}

// ---------------- prep: split x into bf16 hi/lo ----------------
__global__ void prep_x_kernel(const float* __restrict__ x) {
    int i = blockIdx.x * blockDim.x + threadIdx.x;
    const int N4 = T_TOK * D_IN / 4;
    if (i >= N4) return;
    float4 v = reinterpret_cast<const float4*>(x)[i];
    __nv_bfloat16 h0, h1, h2, h3, l0, l1, l2, l3;
    split_bf16(v.x, h0, l0); split_bf16(v.y, h1, l1);
    split_bf16(v.z, h2, l2); split_bf16(v.w, h3, l3);
    __nv_bfloat162* ph = reinterpret_cast<__nv_bfloat162*>(&g_xhi[4 * i]);
    __nv_bfloat162* pl = reinterpret_cast<__nv_bfloat162*>(&g_xlo[4 * i]);
    ph[0] = __halves2bfloat162(h0, h1); ph[1] = __halves2bfloat162(h2, h3);
    pl[0] = __halves2bfloat162(l0, l1); pl[1] = __halves2bfloat162(l2, l3);
}

// ---------------- prep: transpose + split W1 -> [e][H][D] ----------------
__global__ void prep_w1t_kernel(const float* __restrict__ W1) {
    __shared__ float tile[32][33];
    int e = blockIdx.z, n0 = blockIdx.x * 32, k0 = blockIdx.y * 32;
    int tx = threadIdx.x, ty = threadIdx.y;
    const float* W = W1 + (size_t)e * D_IN * H_DIM;
    for (int r = ty; r < 32; r += 8)
        tile[r][tx] = W[(size_t)(k0 + r) * H_DIM + n0 + tx];
    __syncthreads();
    __nv_bfloat16* Hi = g_w1hi + (size_t)e * H_DIM * D_IN;
    __nv_bfloat16* Lo = g_w1lo + (size_t)e * H_DIM * D_IN;
    for (int r = ty; r < 32; r += 8) {
        float v = tile[tx][r];
        __nv_bfloat16 h, l; split_bf16(v, h, l);
        size_t o = (size_t)(n0 + r) * D_IN + k0 + tx;
        Hi[o] = h; Lo[o] = l;
    }
}

// ---------------- prep: transpose + split W2 -> [e][O][H] ----------------
__global__ void prep_w2t_kernel(const float* __restrict__ W2) {
    __shared__ float tile[32][33];
    int e = blockIdx.z, n0 = blockIdx.x * 32, k0 = blockIdx.y * 32;
    int tx = threadIdx.x, ty = threadIdx.y;
    const float* W = W2 + (size_t)e * H_DIM * O_DIM;
    for (int r = ty; r < 32; r += 8)
        tile[r][tx] = W[(size_t)(k0 + r) * O_DIM + n0 + tx];
    __syncthreads();
    __nv_bfloat16* Hi = g_w2hi + (size_t)e * O_DIM * H_DIM;
    __nv_bfloat16* Lo = g_w2lo + (size_t)e * O_DIM * H_DIM;
    for (int r = ty; r < 32; r += 8) {
        float v = tile[tx][r];
        __nv_bfloat16 h, l; split_bf16(v, h, l);
        size_t o = (size_t)(n0 + r) * H_DIM + k0 + tx;
        Hi[o] = h; Lo[o] = l;
    }
}

// ---------------- gate (exact fp32) ----------------
__global__ __launch_bounds__(256) void gate_kernel(
    const float* __restrict__ x, const float* __restrict__ Wg,
    float* __restrict__ gate_out, int write_gate)
{
    __shared__ float sWg[D_IN * NEXP];
    for (int i = threadIdx.x; i < D_IN * NEXP; i += blockDim.x) sWg[i] = Wg[i];
    __syncthreads();

    int warp = threadIdx.x >> 5, lane = threadIdx.x & 31;
    int t = blockIdx.x * 8 + warp;
    const float* xr = x + (size_t)t * D_IN;

    float acc[NEXP];
#pragma unroll
    for (int e = 0; e < NEXP; e++) acc[e] = 0.f;
    for (int d = lane; d < D_IN; d += 32) {
        float xv = xr[d];
#pragma unroll
        for (int e = 0; e < NEXP; e++) acc[e] = fmaf(xv, sWg[d * NEXP + e], acc[e]);
    }
#pragma unroll
    for (int o = 16; o > 0; o >>= 1)
#pragma unroll
        for (int e = 0; e < NEXP; e++) acc[e] += __shfl_xor_sync(0xffffffffu, acc[e], o);

    int i0 = 0; float v0 = acc[0];
#pragma unroll
    for (int e = 1; e < NEXP; e++) if (acc[e] > v0) { v0 = acc[e]; i0 = e; }
    int i1 = -1; float v1 = -3.4e38f;
#pragma unroll
    for (int e = 0; e < NEXP; e++) if (e != i0 && acc[e] > v1) { v1 = acc[e]; i1 = e; }

    float ew = expf(v1 - v0);
    float denom = 1.f + ew;
    float w0 = 1.f / denom, w1 = ew / denom;

    if (write_gate && lane < NEXP)
        gate_out[t * NEXP + lane] = (lane == i0) ? w0 : ((lane == i1) ? w1 : 0.f);
    if (lane == 0) {
        g_tope[2 * t] = i0;     g_topw[2 * t] = w0;
        g_tope[2 * t + 1] = i1; g_topw[2 * t + 1] = w1;
        atomicAdd(&g_cnt[i0], 1);
        atomicAdd(&g_cnt[i1], 1);
    }
}

__global__ void scan_kernel() {
    if (threadIdx.x == 0) {
        int off = 0;
        for (int e = 0; e < NEXP; e++) { g_off[e] = off; g_cursor[e] = off; off += g_cnt[e]; }
    }
}

__global__ void scatter_kernel() {
    int t = blockIdx.x * blockDim.x + threadIdx.x;
    if (t >= T_TOK) return;
#pragma unroll
    for (int k = 0; k < 2; k++) {
        int e = g_tope[2 * t + k];
        float w = g_topw[2 * t + k];
        int pos = atomicAdd(&g_cursor[e], 1);
        g_rowtok[pos] = t;
        g_roww[pos] = w;
    }
}

// ================= FFN GEMM core (mma.sync bf16, 3-term split) =============
// CTA 128x128, 256 thr, warp grid 2(m) x 4(n), warp tile 64x32.
// smem tiles: A[row][k], B[n][k], k-contiguous, 80B padded stride.
// Software-pipelined: next chunk's global loads issue before consuming current.

struct FragState { int wm, wn, g, t; };

__device__ __forceinline__ void gemm_tile_mainloop(
    char* smem, int tid, int KTOT,
    const __nv_bfloat16* Ahi_base, const __nv_bfloat16* Alo_base,
    const int* stokRow,             // nullptr -> contiguous rows from arow0
    size_t arow0, int a_ld,
    const __nv_bfloat16* Bhi_base, const __nv_bfloat16* Blo_base,
    size_t brow0, int b_ld,
    float acc[4][4][4], const FragState& fs)
{
    // per-thread global source pointers (2 A rows, 2 B rows)
    const int rA0 = tid >> 2, segA = (tid & 3) * 16;
    const int rA1 = rA0 + 64;
    size_t ga0 = (stokRow ? (size_t)stokRow[rA0] : (arow0 + rA0)) * a_ld;
    size_t ga1 = (stokRow ? (size_t)stokRow[rA1] : (arow0 + rA1)) * a_ld;
    size_t gb0 = (brow0 + rA0) * b_ld;
    size_t gb1 = (brow0 + rA1) * b_ld;

    uint4 pAh0, pAh1, pAl0, pAl1, pBh0, pBh1, pBl0, pBl1;

    // prologue: fetch chunk 0
    {
        size_t o0 = ga0 * 2 + segA, o1 = ga1 * 2 + segA;
        pAh0 = *(const uint4*)((const char*)Ahi_base + o0);
        pAh1 = *(const uint4*)((const char*)Ahi_base + o1);
        pAl0 = *(const uint4*)((const char*)Alo_base + o0);
        pAl1 = *(const uint4*)((const char*)Alo_base + o1);
        size_t p0 = gb0 * 2 + segA, p1 = gb1 * 2 + segA;
        pBh0 = *(const uint4*)((const char*)Bhi_base + p0);
        pBh1 = *(const uint4*)((const char*)Bhi_base + p1);
        pBl0 = *(const uint4*)((const char*)Blo_base + p0);
        pBl1 = *(const uint4*)((const char*)Blo_base + p1);
    }

    for (int k0 = 0; k0 < KTOT; k0 += BK) {
        // store prefetched chunk into smem
        *(uint4*)(smem + A_HI + rA0 * ROWB + segA) = pAh0;
        *(uint4*)(smem + A_HI + rA1 * ROWB + segA) = pAh1;
        *(uint4*)(smem + A_LO + rA0 * ROWB + segA) = pAl0;
        *(uint4*)(smem + A_LO + rA1 * ROWB + segA) = pAl1;
        *(uint4*)(smem + B_HI + rA0 * ROWB + segA) = pBh0;
        *(uint4*)(smem + B_HI + rA1 * ROWB + segA) = pBh1;
        *(uint4*)(smem + B_LO + rA0 * ROWB + segA) = pBl0;
        *(uint4*)(smem + B_LO + rA1 * ROWB + segA) = pBl1;
        __syncthreads();

        // prefetch next chunk (overlaps with MMA phase below)
        int kn = k0 + BK;
        if (kn < KTOT) {
            size_t o0 = (ga0 + kn) * 2 + segA, o1 = (ga1 + kn) * 2 + segA;
            pAh0 = *(const uint4*)((const char*)Ahi_base + o0);
            pAh1 = *(const uint4*)((const char*)Ahi_base + o1);
            pAl0 = *(const uint4*)((const char*)Alo_base + o0);
            pAl1 = *(const uint4*)((const char*)Alo_base + o1);
            size_t p0 = (gb0 + kn) * 2 + segA, p1 = (gb1 + kn) * 2 + segA;
            pBh0 = *(const uint4*)((const char*)Bhi_base + p0);
            pBh1 = *(const uint4*)((const char*)Bhi_base + p1);
            pBl0 = *(const uint4*)((const char*)Blo_base + p0);
            pBl1 = *(const uint4*)((const char*)Blo_base + p1);
        }

#pragma unroll
        for (int ks = 0; ks < 2; ks++) {
            int kb = (ks * 16 + 2 * fs.t) * 2;   // byte offset in row
            uint32_t ah[4][4], al[4][4];
#pragma unroll
            for (int mf = 0; mf < 4; mf++) {
                const char* b = smem + (fs.wm * 64 + mf * 16 + fs.g) * ROWB + kb;
                ah[mf][0] = *(const uint32_t*)(b + A_HI);
                ah[mf][1] = *(const uint32_t*)(b + A_HI + 8 * ROWB);
                ah[mf][2] = *(const uint32_t*)(b + A_HI + 16);
                ah[mf][3] = *(const uint32_t*)(b + A_HI + 8 * ROWB + 16);
                al[mf][0] = *(const uint32_t*)(b + A_LO);
                al[mf][1] = *(const uint32_t*)(b + A_LO + 8 * ROWB);
                al[mf][2] = *(const uint32_t*)(b + A_LO + 16);
                al[mf][3] = *(const uint32_t*)(b + A_LO + 8 * ROWB + 16);
            }
#pragma unroll
            for (int nf = 0; nf < 4; nf++) {
                const char* bb = smem + (fs.wn * 32 + nf * 8 + fs.g) * ROWB + kb;
                uint32_t bh0 = *(const uint32_t*)(bb + B_HI);
                uint32_t bh1 = *(const uint32_t*)(bb + B_HI + 16);
                uint32_t bl0 = *(const uint32_t*)(bb + B_LO);
                uint32_t bl1 = *(const uint32_t*)(bb + B_LO + 16);
#pragma unroll
                for (int mf = 0; mf < 4; mf++) {
                    mma_bf16(acc[mf][nf], ah[mf], bh0, bh1);
                    mma_bf16(acc[mf][nf], ah[mf], bl0, bl1);
                    mma_bf16(acc[mf][nf], al[mf], bh0, bh1);
                }
            }
        }
        __syncthreads();
    }
}

// ---------------- FFN1: h = gelu(x @ W1 + b1) -------------------------------
__global__ __launch_bounds__(256) void ffn1_mma_kernel(const float* __restrict__ b1)
{
    const int e = blockIdx.z;
    const int cnt = g_cnt[e];
    const int rt = blockIdx.y;
    if (rt * BM >= cnt) return;
    const int m0 = g_off[e] + rt * BM;
    const int n0 = blockIdx.x * BN;

    __shared__ __align__(16) char smem[SMEM_TILE_BYTES];
    __shared__ int stok[BM];

    const int tid = threadIdx.x;
    const int wid = tid >> 5, lane = tid & 31;
    FragState fs;
    fs.wm = wid & 1; fs.wn = wid >> 1; fs.g = lane >> 2; fs.t = lane & 3;

    if (tid < BM) {
        int slot = rt * BM + tid;
        stok[tid] = (slot < cnt) ? g_rowtok[m0 + tid] : g_rowtok[m0];
    }
    __syncthreads();

    float acc[4][4][4];
#pragma unroll
    for (int a = 0; a < 4; a++)
#pragma unroll
        for (int b = 0; b < 4; b++)
#pragma unroll
            for (int c = 0; c < 4; c++) acc[a][b][c] = 0.f;

    gemm_tile_mainloop(smem, tid, D_IN,
                       g_xhi, g_xlo, stok, 0, D_IN,
                       g_w1hi, g_w1lo, (size_t)e * H_DIM + n0, D_IN,
                       acc, fs);

    const float* bb = b1 + e * H_DIM + n0;
#pragma unroll
    for (int mf = 0; mf < 4; mf++) {
#pragma unroll
        for (int half = 0; half < 2; half++) {
            int lrow = fs.wm * 64 + mf * 16 + fs.g + half * 8;
            if (rt * BM + lrow >= cnt) continue;
            size_t gr = m0 + lrow;
#pragma unroll
            for (int nf = 0; nf < 4; nf++) {
                int col = fs.wn * 32 + nf * 8 + 2 * fs.t;
                float v0 = acc[mf][nf][half * 2 + 0] + __ldg(&bb[col]);
                float v1 = acc[mf][nf][half * 2 + 1] + __ldg(&bb[col + 1]);
                v0 = gelu_exact(v0); v1 = gelu_exact(v1);
                __nv_bfloat16 h0, l0, h1, l1;
                split_bf16(v0, h0, l0); split_bf16(v1, h1, l1);
                size_t o = gr * H_DIM + n0 + col;
                *reinterpret_cast<__nv_bfloat162*>(&g_hhi[o]) = __halves2bfloat162(h0, h1);
                *reinterpret_cast<__nv_bfloat162*>(&g_hlo[o]) = __halves2bfloat162(l0, l1);
            }
        }
    }
}

// ---------------- FFN2: out += w * (h @ W2 + b2) ----------------------------
__global__ __launch_bounds__(256) void ffn2_mma_kernel(
    const float* __restrict__ b2, float* __restrict__ out)
{
    const int e = blockIdx.z;
    const int cnt = g_cnt[e];
    const int rt = blockIdx.y;
    if (rt * BM >= cnt) return;
    const int m0 = g_off[e] + rt * BM;
    const int n0 = blockIdx.x * BN;

    __shared__ __align__(16) char smem[SMEM_TILE_BYTES];
    __shared__ int   stok[BM];
    __shared__ float sw[BM];

    const int tid = threadIdx.x;
    const int wid = tid >> 5, lane = tid & 31;
    FragState fs;
    fs.wm = wid & 1; fs.wn = wid >> 1; fs.g = lane >> 2; fs.t = lane & 3;

    if (tid < BM) {
        int slot = rt * BM + tid;
        stok[tid] = (slot < cnt) ? g_rowtok[m0 + tid] : 0;
        sw[tid]   = (slot < cnt) ? g_roww[m0 + tid]  : 0.f;
    }
    __syncthreads();

    float acc[4][4][4];
#pragma unroll
    for (int a = 0; a < 4; a++)
#pragma unroll
        for (int b = 0; b < 4; b++)
#pragma unroll
            for (int c = 0; c < 4; c++) acc[a][b][c] = 0.f;

    gemm_tile_mainloop(smem, tid, H_DIM,
                       g_hhi, g_hlo, nullptr, (size_t)m0, H_DIM,
                       g_w2hi, g_w2lo, (size_t)e * O_DIM + n0, H_DIM,
                       acc, fs);

    const float* bb = b2 + e * O_DIM + n0;
#pragma unroll
    for (int mf = 0; mf < 4; mf++) {
#pragma unroll
        for (int half = 0; half < 2; half++) {
            int lrow = fs.wm * 64 + mf * 16 + fs.g + half * 8;
            if (rt * BM + lrow >= cnt) continue;
            int tkn = stok[lrow];
            float w = sw[lrow];
            float* orow = out + (size_t)tkn * O_DIM + n0;
#pragma unroll
            for (int nf = 0; nf < 4; nf++) {
                int col = fs.wn * 32 + nf * 8 + 2 * fs.t;
                float v0 = (acc[mf][nf][half * 2 + 0] + __ldg(&bb[col]))     * w;
                float v1 = (acc[mf][nf][half * 2 + 1] + __ldg(&bb[col + 1])) * w;
                atomicAdd(&orow[col], v0);
                atomicAdd(&orow[col + 1], v1);
            }
        }
    }
}

// ---------------- launch ----------------
extern "C" void kernel_launch(void* const* d_in, const int* in_sizes, int n_in,
                              void* d_out, int out_size) {
    const float* x  = (const float*)d_in[0];
    const float* Wg = (const float*)d_in[1];
    const float* W1 = (const float*)d_in[2];
    const float* b1 = (const float*)d_in[3];
    const float* W2 = (const float*)d_in[4];
    const float* b2 = (const float*)d_in[5];
    float* out = (float*)d_out;
    int write_gate = (out_size >= OUT_ELEMS + GATE_ELEMS) ? 1 : 0;

    zero_kernel<<<1024, 256>>>(out);
    prep_x_kernel<<<(T_TOK * D_IN / 4 + 255) / 256, 256>>>(x);
    prep_w1t_kernel<<<dim3(H_DIM / 32, D_IN / 32, NEXP), dim3(32, 8)>>>(W1);
    prep_w2t_kernel<<<dim3(O_DIM / 32, H_DIM / 32, NEXP), dim3(32, 8)>>>(W2);
    gate_kernel<<<T_TOK / 8, 256>>>(x, Wg, out + OUT_ELEMS, write_gate);
    scan_kernel<<<1, 32>>>();
    scatter_kernel<<<T_TOK / 256, 256>>>();
    ffn1_mma_kernel<<<dim3(H_DIM / BN, 32, NEXP), 256>>>(b1);
    ffn2_mma_kernel<<<dim3(O_DIM / BN, 32, NEXP), 256>>>(b2, out);
}

// round 12
// speedup vs baseline: 1.9911x; 1.1132x over previous
#include <cuda_runtime.h>
#include <cuda_bf16.h>
#include <math.h>
#include <stdint.h>

// Problem constants
#define T_TOK   4096
#define D_IN    768
#define NEXP    8
#define H_DIM   3072
#define O_DIM   768
#define OUT_ELEMS  (T_TOK * O_DIM)
#define GATE_ELEMS (T_TOK * NEXP)
#define ROWCAP  8320

// GEMM tiling (mma.sync bf16 m16n8k16)
#define BM 128
#define BN 128
#define BK 32
#define ROWB 80               // bytes per smem row (64 data + 16 pad)
// smem byte offsets
#define A_HI 0
#define A_LO (BM * ROWB)
#define B_HI (2 * BM * ROWB)
#define B_LO (2 * BM * ROWB + BN * ROWB)
#define SMEM_TILE_BYTES (2 * BM * ROWB + 2 * BN * ROWB)  // 40960

// ---------------- scratch ----------------
__device__ int   g_cnt[NEXP];
__device__ int   g_off[NEXP];
__device__ int   g_cursor[NEXP];
__device__ int   g_tope[T_TOK * 2];
__device__ float g_topw[T_TOK * 2];
__device__ int   g_rowtok[ROWCAP];
__device__ float g_roww[ROWCAP];

__device__ __nv_bfloat16 g_xhi[T_TOK * D_IN];
__device__ __nv_bfloat16 g_xlo[T_TOK * D_IN];
__device__ __nv_bfloat16 g_w1hi[NEXP * H_DIM * D_IN];   // [e][n][k]
__device__ __nv_bfloat16 g_w1lo[NEXP * H_DIM * D_IN];
__device__ __nv_bfloat16 g_w2hi[NEXP * O_DIM * H_DIM];  // [e][n][k]
__device__ __nv_bfloat16 g_w2lo[NEXP * O_DIM * H_DIM];
__device__ __nv_bfloat16 g_hhi[(size_t)ROWCAP * H_DIM];
__device__ __nv_bfloat16 g_hlo[(size_t)ROWCAP * H_DIM];

// ---------------- helpers ----------------
__device__ __forceinline__ float gelu_exact(float v) {
    return 0.5f * v * (1.0f + erff(v * 0.70710678118654752f));
}
__device__ __forceinline__ void split_bf16(float v, __nv_bfloat16& hi, __nv_bfloat16& lo) {
    hi = __float2bfloat16(v);
    lo = __float2bfloat16(v - __bfloat162float(hi));
}
__device__ __forceinline__ void mma_bf16(float* c, const uint32_t* a,
                                         uint32_t b0, uint32_t b1) {
    asm volatile(
        "mma.sync.aligned.m16n8k16.row.col.f32.bf16.bf16.f32 "
        "{%0,%1,%2,%3}, {%4,%5,%6,%7}, {%8,%9}, {%0,%1,%2,%3};"
        : "+f"(c[0]), "+f"(c[1]), "+f"(c[2]), "+f"(c[3])
        : "r"(a[0]), "r"(a[1]), "r"(a[2]), "r"(a[3]), "r"(b0), "r"(b1));
}
__device__ __forceinline__ void ldsm_x4(uint32_t* r, uint32_t saddr) {
    asm volatile(
        "ldmatrix.sync.aligned.m8n8.x4.shared.b16 {%0,%1,%2,%3}, [%4];"
        : "=r"(r[0]), "=r"(r[1]), "=r"(r[2]), "=r"(r[3]) : "r"(saddr));
}

// ---------------- kernel: zero output + counts ----------------
__global__ void zero_kernel(float* __restrict__ out) {
    int idx = blockIdx.x * blockDim.x + threadIdx.x;
    float4 z = make_float4(0.f, 0.f, 0.f, 0.f);
    float4* o4 = reinterpret_cast<float4*>(out);
    const int n4 = OUT_ELEMS / 4;
    for (int i = idx; i < n4; i += gridDim.x * blockDim.x) o4[i] = z;
    if (idx < NEXP) g_cnt[idx] = 0;
}

// ---------------- prep: split x into bf16 hi/lo ----------------
__global__ void prep_x_kernel(const float* __restrict__ x) {
    int i = blockIdx.x * blockDim.x + threadIdx.x;
    const int N4 = T_TOK * D_IN / 4;
    if (i >= N4) return;
    float4 v = reinterpret_cast<const float4*>(x)[i];
    __nv_bfloat16 h0, h1, h2, h3, l0, l1, l2, l3;
    split_bf16(v.x, h0, l0); split_bf16(v.y, h1, l1);
    split_bf16(v.z, h2, l2); split_bf16(v.w, h3, l3);
    __nv_bfloat162* ph = reinterpret_cast<__nv_bfloat162*>(&g_xhi[4 * i]);
    __nv_bfloat162* pl = reinterpret_cast<__nv_bfloat162*>(&g_xlo[4 * i]);
    ph[0] = __halves2bfloat162(h0, h1); ph[1] = __halves2bfloat162(h2, h3);
    pl[0] = __halves2bfloat162(l0, l1); pl[1] = __halves2bfloat162(l2, l3);
}

// ---------------- prep: transpose + split W -> [e][n][k] --------------------
// 32(n) x 64(k) tile; packed bf162 writes give full 128B coalesced sectors.
__device__ __forceinline__ void prep_wt_tile(
    const float* __restrict__ W, __nv_bfloat16* __restrict__ Hi,
    __nv_bfloat16* __restrict__ Lo, int n0, int k0, int NLD, int KLD)
{
    __shared__ float tile[32][66];   // [n][k], pad 66 for 8B-aligned pairs
    int tx = threadIdx.x, ty = threadIdx.y;
    // load: 64 k-rows x 32 n; reads n-contiguous 128B
    for (int r = ty; r < 64; r += 8)
        tile[tx][r] = W[(size_t)(k0 + r) * NLD + n0 + tx];
    __syncthreads();
    // write: for each n-row r, thread tx packs k = 2tx, 2tx+1
    for (int r = ty; r < 32; r += 8) {
        float v0 = tile[r][2 * tx], v1 = tile[r][2 * tx + 1];
        __nv_bfloat16 h0, l0, h1, l1;
        split_bf16(v0, h0, l0); split_bf16(v1, h1, l1);
        size_t o = (size_t)(n0 + r) * KLD + k0 + 2 * tx;
        *reinterpret_cast<__nv_bfloat162*>(&Hi[o]) = __halves2bfloat162(h0, h1);
        *reinterpret_cast<__nv_bfloat162*>(&Lo[o]) = __halves2bfloat162(l0, l1);
    }
}

__global__ void prep_w1t_kernel(const float* __restrict__ W1) {
    int e = blockIdx.z;
    prep_wt_tile(W1 + (size_t)e * D_IN * H_DIM,
                 g_w1hi + (size_t)e * H_DIM * D_IN,
                 g_w1lo + (size_t)e * H_DIM * D_IN,
                 blockIdx.x * 32, blockIdx.y * 64, H_DIM, D_IN);
}

__global__ void prep_w2t_kernel(const float* __restrict__ W2) {
    int e = blockIdx.z;
    prep_wt_tile(W2 + (size_t)e * H_DIM * O_DIM,
                 g_w2hi + (size_t)e * O_DIM * H_DIM,
                 g_w2lo + (size_t)e * O_DIM * H_DIM,
                 blockIdx.x * 32, blockIdx.y * 64, O_DIM, H_DIM);
}

// ---------------- gate (exact fp32) ----------------
__global__ __launch_bounds__(256) void gate_kernel(
    const float* __restrict__ x, const float* __restrict__ Wg,
    float* __restrict__ gate_out, int write_gate)
{
    __shared__ float sWg[D_IN * NEXP];
    for (int i = threadIdx.x; i < D_IN * NEXP; i += blockDim.x) sWg[i] = Wg[i];
    __syncthreads();

    int warp = threadIdx.x >> 5, lane = threadIdx.x & 31;
    int t = blockIdx.x * 8 + warp;
    const float* xr = x + (size_t)t * D_IN;

    float acc[NEXP];
#pragma unroll
    for (int e = 0; e < NEXP; e++) acc[e] = 0.f;
    for (int d = lane; d < D_IN; d += 32) {
        float xv = xr[d];
#pragma unroll
        for (int e = 0; e < NEXP; e++) acc[e] = fmaf(xv, sWg[d * NEXP + e], acc[e]);
    }
#pragma unroll
    for (int o = 16; o > 0; o >>= 1)
#pragma unroll
        for (int e = 0; e < NEXP; e++) acc[e] += __shfl_xor_sync(0xffffffffu, acc[e], o);

    int i0 = 0; float v0 = acc[0];
#pragma unroll
    for (int e = 1; e < NEXP; e++) if (acc[e] > v0) { v0 = acc[e]; i0 = e; }
    int i1 = -1; float v1 = -3.4e38f;
#pragma unroll
    for (int e = 0; e < NEXP; e++) if (e != i0 && acc[e] > v1) { v1 = acc[e]; i1 = e; }

    float ew = expf(v1 - v0);
    float denom = 1.f + ew;
    float w0 = 1.f / denom, w1 = ew / denom;

    if (write_gate && lane < NEXP)
        gate_out[t * NEXP + lane] = (lane == i0) ? w0 : ((lane == i1) ? w1 : 0.f);
    if (lane == 0) {
        g_tope[2 * t] = i0;     g_topw[2 * t] = w0;
        g_tope[2 * t + 1] = i1; g_topw[2 * t + 1] = w1;
        atomicAdd(&g_cnt[i0], 1);
        atomicAdd(&g_cnt[i1], 1);
    }
}

__global__ void scan_kernel() {
    if (threadIdx.x == 0) {
        int off = 0;
        for (int e = 0; e < NEXP; e++) { g_off[e] = off; g_cursor[e] = off; off += g_cnt[e]; }
    }
}

__global__ void scatter_kernel() {
    int t = blockIdx.x * blockDim.x + threadIdx.x;
    if (t >= T_TOK) return;
#pragma unroll
    for (int k = 0; k < 2; k++) {
        int e = g_tope[2 * t + k];
        float w = g_topw[2 * t + k];
        int pos = atomicAdd(&g_cursor[e], 1);
        g_rowtok[pos] = t;
        g_roww[pos] = w;
    }
}

// ================= FFN GEMM core (mma.sync bf16, 3-term split) =============
// CTA 128x128, 256 thr, warp grid 2(m) x 4(n), warp tile 64x32.
// smem tiles: A[row][k], B[n][k], 80B padded stride (conflict-free ldmatrix).
// ldmatrix.x4 fragment loads (4x fewer shared-load instructions than LDS.32).
// Register-prefetch software pipeline for global loads.

struct FragState { int wm, wn; };

__device__ __forceinline__ void gemm_tile_mainloop(
    char* smem, int tid, int KTOT,
    const __nv_bfloat16* Ahi_base, const __nv_bfloat16* Alo_base,
    const int* stokRow,             // nullptr -> contiguous rows from arow0
    size_t arow0, int a_ld,
    const __nv_bfloat16* Bhi_base, const __nv_bfloat16* Blo_base,
    size_t brow0, int b_ld,
    float acc[4][4][4], const FragState& fs)
{
    // per-thread global source pointers (2 A rows, 2 B rows)
    const int rA0 = tid >> 2, segA = (tid & 3) * 16;
    const int rA1 = rA0 + 64;
    size_t ga0 = (stokRow ? (size_t)stokRow[rA0] : (arow0 + rA0)) * a_ld;
    size_t ga1 = (stokRow ? (size_t)stokRow[rA1] : (arow0 + rA1)) * a_ld;
    size_t gb0 = (brow0 + rA0) * b_ld;
    size_t gb1 = (brow0 + rA1) * b_ld;

    // ldmatrix lane address patterns
    const int lane = tid & 31;
    const int quad = lane >> 3, lr = lane & 7;
    const uint32_t s_base = (uint32_t)__cvta_generic_to_shared(smem);
    const uint32_t laneA = ((quad & 1) * 8 + lr) * ROWB + (quad >> 1) * 16;
    const uint32_t laneB = ((quad >> 1) * 8 + lr) * ROWB + (quad & 1) * 16;
    const uint32_t aBase = s_base + A_HI + (fs.wm * 64) * ROWB + laneA;
    const uint32_t bBase = s_base + B_HI + (fs.wn * 32) * ROWB + laneB;

    uint4 pAh0, pAh1, pAl0, pAl1, pBh0, pBh1, pBl0, pBl1;

    // prologue: fetch chunk 0
    {
        size_t o0 = ga0 * 2 + segA, o1 = ga1 * 2 + segA;
        pAh0 = *(const uint4*)((const char*)Ahi_base + o0);
        pAh1 = *(const uint4*)((const char*)Ahi_base + o1);
        pAl0 = *(const uint4*)((const char*)Alo_base + o0);
        pAl1 = *(const uint4*)((const char*)Alo_base + o1);
        size_t p0 = gb0 * 2 + segA, p1 = gb1 * 2 + segA;
        pBh0 = *(const uint4*)((const char*)Bhi_base + p0);
        pBh1 = *(const uint4*)((const char*)Bhi_base + p1);
        pBl0 = *(const uint4*)((const char*)Blo_base + p0);
        pBl1 = *(const uint4*)((const char*)Blo_base + p1);
    }

    for (int k0 = 0; k0 < KTOT; k0 += BK) {
        // store prefetched chunk into smem
        *(uint4*)(smem + A_HI + rA0 * ROWB + segA) = pAh0;
        *(uint4*)(smem + A_HI + rA1 * ROWB + segA) = pAh1;
        *(uint4*)(smem + A_LO + rA0 * ROWB + segA) = pAl0;
        *(uint4*)(smem + A_LO + rA1 * ROWB + segA) = pAl1;
        *(uint4*)(smem + B_HI + rA0 * ROWB + segA) = pBh0;
        *(uint4*)(smem + B_HI + rA1 * ROWB + segA) = pBh1;
        *(uint4*)(smem + B_LO + rA0 * ROWB + segA) = pBl0;
        *(uint4*)(smem + B_LO + rA1 * ROWB + segA) = pBl1;
        __syncthreads();

        // prefetch next chunk (overlaps with MMA phase below)
        int kn = k0 + BK;
        if (kn < KTOT) {
            size_t o0 = (ga0 + kn) * 2 + segA, o1 = (ga1 + kn) * 2 + segA;
            pAh0 = *(const uint4*)((const char*)Ahi_base + o0);
            pAh1 = *(const uint4*)((const char*)Ahi_base + o1);
            pAl0 = *(const uint4*)((const char*)Alo_base + o0);
            pAl1 = *(const uint4*)((const char*)Alo_base + o1);
            size_t p0 = (gb0 + kn) * 2 + segA, p1 = (gb1 + kn) * 2 + segA;
            pBh0 = *(const uint4*)((const char*)Bhi_base + p0);
            pBh1 = *(const uint4*)((const char*)Bhi_base + p1);
            pBl0 = *(const uint4*)((const char*)Blo_base + p0);
            pBl1 = *(const uint4*)((const char*)Blo_base + p1);
        }

#pragma unroll
        for (int ks = 0; ks < 2; ks++) {
            uint32_t ah[4][4], al[4][4];
#pragma unroll
            for (int mf = 0; mf < 4; mf++) {
                uint32_t aaddr = aBase + mf * 16 * ROWB + ks * 32;
                ldsm_x4(ah[mf], aaddr);
                ldsm_x4(al[mf], aaddr + (A_LO - A_HI));
            }
#pragma unroll
            for (int pair = 0; pair < 2; pair++) {
                uint32_t baddr = bBase + pair * 16 * ROWB + ks * 32;
                uint32_t bh4[4], bl4[4];
                ldsm_x4(bh4, baddr);
                ldsm_x4(bl4, baddr + (B_LO - B_HI));
#pragma unroll
                for (int mf = 0; mf < 4; mf++) {
                    mma_bf16(acc[mf][2 * pair],     ah[mf], bh4[0], bh4[1]);
                    mma_bf16(acc[mf][2 * pair],     ah[mf], bl4[0], bl4[1]);
                    mma_bf16(acc[mf][2 * pair],     al[mf], bh4[0], bh4[1]);
                    mma_bf16(acc[mf][2 * pair + 1], ah[mf], bh4[2], bh4[3]);
                    mma_bf16(acc[mf][2 * pair + 1], ah[mf], bl4[2], bl4[3]);
                    mma_bf16(acc[mf][2 * pair + 1], al[mf], bh4[2], bh4[3]);
                }
            }
        }
        __syncthreads();
    }
}

// ---------------- FFN1: h = gelu(x @ W1 + b1) -------------------------------
__global__ __launch_bounds__(256) void ffn1_mma_kernel(const float* __restrict__ b1)
{
    const int e = blockIdx.z;
    const int cnt = g_cnt[e];
    const int rt = blockIdx.y;
    if (rt * BM >= cnt) return;
    const int m0 = g_off[e] + rt * BM;
    const int n0 = blockIdx.x * BN;

    __shared__ __align__(16) char smem[SMEM_TILE_BYTES];
    __shared__ int stok[BM];

    const int tid = threadIdx.x;
    const int wid = tid >> 5, lane = tid & 31;
    FragState fs;
    fs.wm = wid & 1; fs.wn = wid >> 1;
    const int g = lane >> 2, t4 = lane & 3;

    if (tid < BM) {
        int slot = rt * BM + tid;
        stok[tid] = (slot < cnt) ? g_rowtok[m0 + tid] : g_rowtok[m0];
    }
    __syncthreads();

    float acc[4][4][4];
#pragma unroll
    for (int a = 0; a < 4; a++)
#pragma unroll
        for (int b = 0; b < 4; b++)
#pragma unroll
            for (int c = 0; c < 4; c++) acc[a][b][c] = 0.f;

    gemm_tile_mainloop(smem, tid, D_IN,
                       g_xhi, g_xlo, stok, 0, D_IN,
                       g_w1hi, g_w1lo, (size_t)e * H_DIM + n0, D_IN,
                       acc, fs);

    const float* bb = b1 + e * H_DIM + n0;
#pragma unroll
    for (int mf = 0; mf < 4; mf++) {
#pragma unroll
        for (int half = 0; half < 2; half++) {
            int lrow = fs.wm * 64 + mf * 16 + g + half * 8;
            if (rt * BM + lrow >= cnt) continue;
            size_t gr = m0 + lrow;
#pragma unroll
            for (int nf = 0; nf < 4; nf++) {
                int col = fs.wn * 32 + nf * 8 + 2 * t4;
                float v0 = acc[mf][nf][half * 2 + 0] + __ldg(&bb[col]);
                float v1 = acc[mf][nf][half * 2 + 1] + __ldg(&bb[col + 1]);
                v0 = gelu_exact(v0); v1 = gelu_exact(v1);
                __nv_bfloat16 h0, l0, h1, l1;
                split_bf16(v0, h0, l0); split_bf16(v1, h1, l1);
                size_t o = gr * H_DIM + n0 + col;
                *reinterpret_cast<__nv_bfloat162*>(&g_hhi[o]) = __halves2bfloat162(h0, h1);
                *reinterpret_cast<__nv_bfloat162*>(&g_hlo[o]) = __halves2bfloat162(l0, l1);
            }
        }
    }
}

// ---------------- FFN2: out += w * (h @ W2 + b2) ----------------------------
__global__ __launch_bounds__(256) void ffn2_mma_kernel(
    const float* __restrict__ b2, float* __restrict__ out)
{
    const int e = blockIdx.z;
    const int cnt = g_cnt[e];
    const int rt = blockIdx.y;
    if (rt * BM >= cnt) return;
    const int m0 = g_off[e] + rt * BM;
    const int n0 = blockIdx.x * BN;

    __shared__ __align__(16) char smem[SMEM_TILE_BYTES];
    __shared__ int   stok[BM];
    __shared__ float sw[BM];

    const int tid = threadIdx.x;
    const int wid = tid >> 5, lane = tid & 31;
    FragState fs;
    fs.wm = wid & 1; fs.wn = wid >> 1;
    const int g = lane >> 2, t4 = lane & 3;

    if (tid < BM) {
        int slot = rt * BM + tid;
        stok[tid] = (slot < cnt) ? g_rowtok[m0 + tid] : 0;
        sw[tid]   = (slot < cnt) ? g_roww[m0 + tid]  : 0.f;
    }
    __syncthreads();

    float acc[4][4][4];
#pragma unroll
    for (int a = 0; a < 4; a++)
#pragma unroll
        for (int b = 0; b < 4; b++)
#pragma unroll
            for (int c = 0; c < 4; c++) acc[a][b][c] = 0.f;

    gemm_tile_mainloop(smem, tid, H_DIM,
                       g_hhi, g_hlo, nullptr, (size_t)m0, H_DIM,
                       g_w2hi, g_w2lo, (size_t)e * O_DIM + n0, H_DIM,
                       acc, fs);

    const float* bb = b2 + e * O_DIM + n0;
#pragma unroll
    for (int mf = 0; mf < 4; mf++) {
#pragma unroll
        for (int half = 0; half < 2; half++) {
            int lrow = fs.wm * 64 + mf * 16 + g + half * 8;
            if (rt * BM + lrow >= cnt) continue;
            int tkn = stok[lrow];
            float w = sw[lrow];
            float* orow = out + (size_t)tkn * O_DIM + n0;
#pragma unroll
            for (int nf = 0; nf < 4; nf++) {
                int col = fs.wn * 32 + nf * 8 + 2 * t4;
                float v0 = (acc[mf][nf][half * 2 + 0] + __ldg(&bb[col]))     * w;
                float v1 = (acc[mf][nf][half * 2 + 1] + __ldg(&bb[col + 1])) * w;
                atomicAdd(&orow[col], v0);
                atomicAdd(&orow[col + 1], v1);
            }
        }
    }
}

// ---------------- launch ----------------
extern "C" void kernel_launch(void* const* d_in, const int* in_sizes, int n_in,
                              void* d_out, int out_size) {
    const float* x  = (const float*)d_in[0];
    const float* Wg = (const float*)d_in[1];
    const float* W1 = (const float*)d_in[2];
    const float* b1 = (const float*)d_in[3];
    const float* W2 = (const float*)d_in[4];
    const float* b2 = (const float*)d_in[5];
    float* out = (float*)d_out;
    int write_gate = (out_size >= OUT_ELEMS + GATE_ELEMS) ? 1 : 0;

    zero_kernel<<<1024, 256>>>(out);
    prep_x_kernel<<<(T_TOK * D_IN / 4 + 255) / 256, 256>>>(x);
    prep_w1t_kernel<<<dim3(H_DIM / 32, D_IN / 64, NEXP), dim3(32, 8)>>>(W1);
    prep_w2t_kernel<<<dim3(O_DIM / 32, H_DIM / 64, NEXP), dim3(32, 8)>>>(W2);
    gate_kernel<<<T_TOK / 8, 256>>>(x, Wg, out + OUT_ELEMS, write_gate);
    scan_kernel<<<1, 32>>>();
    scatter_kernel<<<T_TOK / 256, 256>>>();
    ffn1_mma_kernel<<<dim3(H_DIM / BN, 32, NEXP), 256>>>(b1);
    ffn2_mma_kernel<<<dim3(O_DIM / BN, 32, NEXP), 256>>>(b2, out);
}

// round 14
// speedup vs baseline: 2.1942x; 1.1020x over previous
#include <cuda_runtime.h>
#include <cuda_bf16.h>
#include <math.h>
#include <stdint.h>

// Problem constants
#define T_TOK   4096
#define D_IN    768
#define NEXP    8
#define H_DIM   3072
#define O_DIM   768
#define OUT_ELEMS  (T_TOK * O_DIM)
#define GATE_ELEMS (T_TOK * NEXP)
#define ROWCAP  8320

// GEMM tiling (mma.sync bf16 m16n8k16)
#define BM 128
#define BN 128
#define BK 32
#define ROWB 80               // bytes per smem row (64 data + 16 pad)
// smem byte offsets within one stage
#define A_HI 0
#define A_LO (BM * ROWB)
#define B_HI (2 * BM * ROWB)
#define B_LO (2 * BM * ROWB + BN * ROWB)
#define STAGE_BYTES (2 * BM * ROWB + 2 * BN * ROWB)   // 40960
#define SMEM_ALLOC (2 * STAGE_BYTES)                  // 81920 (2-stage)

// ---------------- scratch ----------------
__device__ int   g_cnt[NEXP];
__device__ int   g_off[NEXP];
__device__ int   g_cursor[NEXP];
__device__ int   g_tope[T_TOK * 2];
__device__ float g_topw[T_TOK * 2];
__device__ int   g_rowtok[ROWCAP];
__device__ float g_roww[ROWCAP];

__device__ __nv_bfloat16 g_xhi[T_TOK * D_IN];
__device__ __nv_bfloat16 g_xlo[T_TOK * D_IN];
__device__ __nv_bfloat16 g_w1hi[NEXP * H_DIM * D_IN];   // [e][n][k]
__device__ __nv_bfloat16 g_w1lo[NEXP * H_DIM * D_IN];
__device__ __nv_bfloat16 g_w2hi[NEXP * O_DIM * H_DIM];  // [e][n][k]
__device__ __nv_bfloat16 g_w2lo[NEXP * O_DIM * H_DIM];
__device__ __nv_bfloat16 g_hhi[(size_t)ROWCAP * H_DIM];
__device__ __nv_bfloat16 g_hlo[(size_t)ROWCAP * H_DIM];

// ---------------- helpers ----------------
__device__ __forceinline__ float gelu_exact(float v) {
    return 0.5f * v * (1.0f + erff(v * 0.70710678118654752f));
}
__device__ __forceinline__ void split_bf16(float v, __nv_bfloat16& hi, __nv_bfloat16& lo) {
    hi = __float2bfloat16(v);
    lo = __float2bfloat16(v - __bfloat162float(hi));
}
__device__ __forceinline__ void mma_bf16(float* c, const uint32_t* a,
                                         uint32_t b0, uint32_t b1) {
    asm volatile(
        "mma.sync.aligned.m16n8k16.row.col.f32.bf16.bf16.f32 "
        "{%0,%1,%2,%3}, {%4,%5,%6,%7}, {%8,%9}, {%0,%1,%2,%3};"
        : "+f"(c[0]), "+f"(c[1]), "+f"(c[2]), "+f"(c[3])
        : "r"(a[0]), "r"(a[1]), "r"(a[2]), "r"(a[3]), "r"(b0), "r"(b1));
}
__device__ __forceinline__ void ldsm_x4(uint32_t* r, uint32_t saddr) {
    asm volatile(
        "ldmatrix.sync.aligned.m8n8.x4.shared.b16 {%0,%1,%2,%3}, [%4];"
        : "=r"(r[0]), "=r"(r[1]), "=r"(r[2]), "=r"(r[3]) : "r"(saddr));
}
__device__ __forceinline__ void cp16(uint32_t dst, const void* src) {
    asm volatile("cp.async.cg.shared.global [%0], [%1], 16;"
                 :: "r"(dst), "l"(src) : "memory");
}
__device__ __forceinline__ void cp_commit() {
    asm volatile("cp.async.commit_group;" ::: "memory");
}
template <int N>
__device__ __forceinline__ void cp_wait() {
    asm volatile("cp.async.wait_group %0;" :: "n"(N) : "memory");
}

// ---------------- kernel: zero output + counts ----------------
__global__ void zero_kernel(float* __restrict__ out) {
    int idx = blockIdx.x * blockDim.x + threadIdx.x;
    float4 z = make_float4(0.f, 0.f, 0.f, 0.f);
    float4* o4 = reinterpret_cast<float4*>(out);
    const int n4 = OUT_ELEMS / 4;
    for (int i = idx; i < n4; i += gridDim.x * blockDim.x) o4[i] = z;
    if (idx < NEXP) g_cnt[idx] = 0;
}

// ---------------- prep: split x into bf16 hi/lo ----------------
__global__ void prep_x_kernel(const float* __restrict__ x) {
    int i = blockIdx.x * blockDim.x + threadIdx.x;
    const int N4 = T_TOK * D_IN / 4;
    if (i >= N4) return;
    float4 v = reinterpret_cast<const float4*>(x)[i];
    __nv_bfloat16 h0, h1, h2, h3, l0, l1, l2, l3;
    split_bf16(v.x, h0, l0); split_bf16(v.y, h1, l1);
    split_bf16(v.z, h2, l2); split_bf16(v.w, h3, l3);
    __nv_bfloat162* ph = reinterpret_cast<__nv_bfloat162*>(&g_xhi[4 * i]);
    __nv_bfloat162* pl = reinterpret_cast<__nv_bfloat162*>(&g_xlo[4 * i]);
    ph[0] = __halves2bfloat162(h0, h1); ph[1] = __halves2bfloat162(h2, h3);
    pl[0] = __halves2bfloat162(l0, l1); pl[1] = __halves2bfloat162(l2, l3);
}

// ---------------- prep: transpose + split W -> [e][n][k] --------------------
__device__ __forceinline__ void prep_wt_tile(
    const float* __restrict__ W, __nv_bfloat16* __restrict__ Hi,
    __nv_bfloat16* __restrict__ Lo, int n0, int k0, int NLD, int KLD)
{
    __shared__ float tile[32][66];
    int tx = threadIdx.x, ty = threadIdx.y;
    for (int r = ty; r < 64; r += 8)
        tile[tx][r] = W[(size_t)(k0 + r) * NLD + n0 + tx];
    __syncthreads();
    for (int r = ty; r < 32; r += 8) {
        float v0 = tile[r][2 * tx], v1 = tile[r][2 * tx + 1];
        __nv_bfloat16 h0, l0, h1, l1;
        split_bf16(v0, h0, l0); split_bf16(v1, h1, l1);
        size_t o = (size_t)(n0 + r) * KLD + k0 + 2 * tx;
        *reinterpret_cast<__nv_bfloat162*>(&Hi[o]) = __halves2bfloat162(h0, h1);
        *reinterpret_cast<__nv_bfloat162*>(&Lo[o]) = __halves2bfloat162(l0, l1);
    }
}

__global__ void prep_w1t_kernel(const float* __restrict__ W1) {
    int e = blockIdx.z;
    prep_wt_tile(W1 + (size_t)e * D_IN * H_DIM,
                 g_w1hi + (size_t)e * H_DIM * D_IN,
                 g_w1lo + (size_t)e * H_DIM * D_IN,
                 blockIdx.x * 32, blockIdx.y * 64, H_DIM, D_IN);
}

__global__ void prep_w2t_kernel(const float* __restrict__ W2) {
    int e = blockIdx.z;
    prep_wt_tile(W2 + (size_t)e * H_DIM * O_DIM,
                 g_w2hi + (size_t)e * O_DIM * H_DIM,
                 g_w2lo + (size_t)e * O_DIM * H_DIM,
                 blockIdx.x * 32, blockIdx.y * 64, O_DIM, H_DIM);
}

// ---------------- gate (exact fp32) ----------------
__global__ __launch_bounds__(256) void gate_kernel(
    const float* __restrict__ x, const float* __restrict__ Wg,
    float* __restrict__ gate_out, int write_gate)
{
    __shared__ float sWg[D_IN * NEXP];
    for (int i = threadIdx.x; i < D_IN * NEXP; i += blockDim.x) sWg[i] = Wg[i];
    __syncthreads();

    int warp = threadIdx.x >> 5, lane = threadIdx.x & 31;
    int t = blockIdx.x * 8 + warp;
    const float* xr = x + (size_t)t * D_IN;

    float acc[NEXP];
#pragma unroll
    for (int e = 0; e < NEXP; e++) acc[e] = 0.f;
    for (int d = lane; d < D_IN; d += 32) {
        float xv = xr[d];
#pragma unroll
        for (int e = 0; e < NEXP; e++) acc[e] = fmaf(xv, sWg[d * NEXP + e], acc[e]);
    }
#pragma unroll
    for (int o = 16; o > 0; o >>= 1)
#pragma unroll
        for (int e = 0; e < NEXP; e++) acc[e] += __shfl_xor_sync(0xffffffffu, acc[e], o);

    int i0 = 0; float v0 = acc[0];
#pragma unroll
    for (int e = 1; e < NEXP; e++) if (acc[e] > v0) { v0 = acc[e]; i0 = e; }
    int i1 = -1; float v1 = -3.4e38f;
#pragma unroll
    for (int e = 0; e < NEXP; e++) if (e != i0 && acc[e] > v1) { v1 = acc[e]; i1 = e; }

    float ew = expf(v1 - v0);
    float denom = 1.f + ew;
    float w0 = 1.f / denom, w1 = ew / denom;

    if (write_gate && lane < NEXP)
        gate_out[t * NEXP + lane] = (lane == i0) ? w0 : ((lane == i1) ? w1 : 0.f);
    if (lane == 0) {
        g_tope[2 * t] = i0;     g_topw[2 * t] = w0;
        g_tope[2 * t + 1] = i1; g_topw[2 * t + 1] = w1;
        atomicAdd(&g_cnt[i0], 1);
        atomicAdd(&g_cnt[i1], 1);
    }
}

__global__ void scan_kernel() {
    if (threadIdx.x == 0) {
        int off = 0;
        for (int e = 0; e < NEXP; e++) { g_off[e] = off; g_cursor[e] = off; off += g_cnt[e]; }
    }
}

__global__ void scatter_kernel() {
    int t = blockIdx.x * blockDim.x + threadIdx.x;
    if (t >= T_TOK) return;
#pragma unroll
    for (int k = 0; k < 2; k++) {
        int e = g_tope[2 * t + k];
        float w = g_topw[2 * t + k];
        int pos = atomicAdd(&g_cursor[e], 1);
        g_rowtok[pos] = t;
        g_roww[pos] = w;
    }
}

// ================= FFN GEMM core (mma.sync bf16, 3-term split) =============
// CTA 128x128, 256 thr, warp grid 2(m) x 4(n), warp tile 64x32.
// 2-stage cp.async pipeline; ldmatrix.x4 fragment loads; 80B padded stride.

struct FragState { int wm, wn; };

__device__ __forceinline__ void gemm_tile_mainloop(
    char* smem, int tid, int KTOT,
    const __nv_bfloat16* Ahi_base, const __nv_bfloat16* Alo_base,
    const int* stokRow,             // nullptr -> contiguous rows from arow0
    size_t arow0, int a_ld,
    const __nv_bfloat16* Bhi_base, const __nv_bfloat16* Blo_base,
    size_t brow0, int b_ld,
    float acc[4][4][4], const FragState& fs)
{
    // per-thread fill assignment (2 A rows, 2 B rows; 16B each)
    const int rA0 = tid >> 2, segA = (tid & 3) * 16;
    const int rA1 = rA0 + 64;
    size_t ga0 = (stokRow ? (size_t)stokRow[rA0] : (arow0 + rA0)) * a_ld;
    size_t ga1 = (stokRow ? (size_t)stokRow[rA1] : (arow0 + rA1)) * a_ld;
    size_t gb0 = (brow0 + rA0) * b_ld;
    size_t gb1 = (brow0 + rA1) * b_ld;

    const uint32_t s_base = (uint32_t)__cvta_generic_to_shared(smem);
    const uint32_t dA0 = s_base + A_HI + rA0 * ROWB + segA;
    const uint32_t dA1 = s_base + A_HI + rA1 * ROWB + segA;
    const uint32_t dB0 = s_base + B_HI + rA0 * ROWB + segA;
    const uint32_t dB1 = s_base + B_HI + rA1 * ROWB + segA;

    // ldmatrix lane address patterns
    const int lane = tid & 31;
    const int quad = lane >> 3, lr = lane & 7;
    const uint32_t laneA = ((quad & 1) * 8 + lr) * ROWB + (quad >> 1) * 16;
    const uint32_t laneB = ((quad >> 1) * 8 + lr) * ROWB + (quad & 1) * 16;
    const uint32_t aBase0 = s_base + A_HI + (fs.wm * 64) * ROWB + laneA;
    const uint32_t bBase0 = s_base + B_HI + (fs.wn * 32) * ROWB + laneB;

    const int NCH = KTOT / BK;

    // fill helper (lambda): stage st, k-offset k0
    auto fill = [&](int st, int k0) {
        uint32_t so = (uint32_t)(st * STAGE_BYTES);
        size_t o0 = (ga0 + k0) * 2 + segA, o1 = (ga1 + k0) * 2 + segA;
        cp16(dA0 + so,                (const char*)Ahi_base + o0);
        cp16(dA1 + so,                (const char*)Ahi_base + o1);
        cp16(dA0 + so + (A_LO - A_HI), (const char*)Alo_base + o0);
        cp16(dA1 + so + (A_LO - A_HI), (const char*)Alo_base + o1);
        size_t p0 = (gb0 + k0) * 2 + segA, p1 = (gb1 + k0) * 2 + segA;
        cp16(dB0 + so,                (const char*)Bhi_base + p0);
        cp16(dB1 + so,                (const char*)Bhi_base + p1);
        cp16(dB0 + so + (B_LO - B_HI), (const char*)Blo_base + p0);
        cp16(dB1 + so + (B_LO - B_HI), (const char*)Blo_base + p1);
    };

    fill(0, 0);
    cp_commit();

    for (int ic = 0; ic < NCH; ic++) {
        if (ic + 1 < NCH) {
            fill((ic + 1) & 1, (ic + 1) * BK);
            cp_commit();
            cp_wait<1>();
        } else {
            cp_wait<0>();
        }
        __syncthreads();

        const uint32_t so = (uint32_t)((ic & 1) * STAGE_BYTES);
        const uint32_t aBase = aBase0 + so;
        const uint32_t bBase = bBase0 + so;

#pragma unroll
        for (int ks = 0; ks < 2; ks++) {
            uint32_t ah[4][4], al[4][4];
#pragma unroll
            for (int mf = 0; mf < 4; mf++) {
                uint32_t aaddr = aBase + mf * 16 * ROWB + ks * 32;
                ldsm_x4(ah[mf], aaddr);
                ldsm_x4(al[mf], aaddr + (A_LO - A_HI));
            }
#pragma unroll
            for (int pair = 0; pair < 2; pair++) {
                uint32_t baddr = bBase + pair * 16 * ROWB + ks * 32;
                uint32_t bh4[4], bl4[4];
                ldsm_x4(bh4, baddr);
                ldsm_x4(bl4, baddr + (B_LO - B_HI));
#pragma unroll
                for (int mf = 0; mf < 4; mf++) {
                    mma_bf16(acc[mf][2 * pair],     ah[mf], bh4[0], bh4[1]);
                    mma_bf16(acc[mf][2 * pair],     ah[mf], bl4[0], bl4[1]);
                    mma_bf16(acc[mf][2 * pair],     al[mf], bh4[0], bh4[1]);
                    mma_bf16(acc[mf][2 * pair + 1], ah[mf], bh4[2], bh4[3]);
                    mma_bf16(acc[mf][2 * pair + 1], ah[mf], bl4[2], bl4[3]);
                    mma_bf16(acc[mf][2 * pair + 1], al[mf], bh4[2], bh4[3]);
                }
            }
        }
        __syncthreads();
    }
}

// ---------------- FFN1: h = gelu(x @ W1 + b1) -------------------------------
__global__ __launch_bounds__(256, 2) void ffn1_mma_kernel(const float* __restrict__ b1)
{
    const int e = blockIdx.z;
    const int cnt = g_cnt[e];
    const int rt = blockIdx.y;
    if (rt * BM >= cnt) return;
    const int m0 = g_off[e] + rt * BM;
    const int n0 = blockIdx.x * BN;

    extern __shared__ __align__(16) char smem[];
    __shared__ int stok[BM];

    const int tid = threadIdx.x;
    const int wid = tid >> 5, lane = tid & 31;
    FragState fs;
    fs.wm = wid & 1; fs.wn = wid >> 1;
    const int g = lane >> 2, t4 = lane & 3;

    if (tid < BM) {
        int slot = rt * BM + tid;
        stok[tid] = (slot < cnt) ? g_rowtok[m0 + tid] : g_rowtok[m0];
    }
    __syncthreads();

    float acc[4][4][4];
#pragma unroll
    for (int a = 0; a < 4; a++)
#pragma unroll
        for (int b = 0; b < 4; b++)
#pragma unroll
            for (int c = 0; c < 4; c++) acc[a][b][c] = 0.f;

    gemm_tile_mainloop(smem, tid, D_IN,
                       g_xhi, g_xlo, stok, 0, D_IN,
                       g_w1hi, g_w1lo, (size_t)e * H_DIM + n0, D_IN,
                       acc, fs);

    const float* bb = b1 + e * H_DIM + n0;
#pragma unroll
    for (int mf = 0; mf < 4; mf++) {
#pragma unroll
        for (int half = 0; half < 2; half++) {
            int lrow = fs.wm * 64 + mf * 16 + g + half * 8;
            if (rt * BM + lrow >= cnt) continue;
            size_t gr = m0 + lrow;
#pragma unroll
            for (int nf = 0; nf < 4; nf++) {
                int col = fs.wn * 32 + nf * 8 + 2 * t4;
                float v0 = acc[mf][nf][half * 2 + 0] + __ldg(&bb[col]);
                float v1 = acc[mf][nf][half * 2 + 1] + __ldg(&bb[col + 1]);
                v0 = gelu_exact(v0); v1 = gelu_exact(v1);
                __nv_bfloat16 h0, l0, h1, l1;
                split_bf16(v0, h0, l0); split_bf16(v1, h1, l1);
                size_t o = gr * H_DIM + n0 + col;
                *reinterpret_cast<__nv_bfloat162*>(&g_hhi[o]) = __halves2bfloat162(h0, h1);
                *reinterpret_cast<__nv_bfloat162*>(&g_hlo[o]) = __halves2bfloat162(l0, l1);
            }
        }
    }
}

// ---------------- FFN2: out += w * (h @ W2 + b2) ----------------------------
__global__ __launch_bounds__(256, 2) void ffn2_mma_kernel(
    const float* __restrict__ b2, float* __restrict__ out)
{
    const int e = blockIdx.z;
    const int cnt = g_cnt[e];
    const int rt = blockIdx.y;
    if (rt * BM >= cnt) return;
    const int m0 = g_off[e] + rt * BM;
    const int n0 = blockIdx.x * BN;

    extern __shared__ __align__(16) char smem[];
    __shared__ int   stok[BM];
    __shared__ float sw[BM];

    const int tid = threadIdx.x;
    const int wid = tid >> 5, lane = tid & 31;
    FragState fs;
    fs.wm = wid & 1; fs.wn = wid >> 1;
    const int g = lane >> 2, t4 = lane & 3;

    if (tid < BM) {
        int slot = rt * BM + tid;
        stok[tid] = (slot < cnt) ? g_rowtok[m0 + tid] : 0;
        sw[tid]   = (slot < cnt) ? g_roww[m0 + tid]  : 0.f;
    }
    __syncthreads();

    float acc[4][4][4];
#pragma unroll
    for (int a = 0; a < 4; a++)
#pragma unroll
        for (int b = 0; b < 4; b++)
#pragma unroll
            for (int c = 0; c < 4; c++) acc[a][b][c] = 0.f;

    gemm_tile_mainloop(smem, tid, H_DIM,
                       g_hhi, g_hlo, nullptr, (size_t)m0, H_DIM,
                       g_w2hi, g_w2lo, (size_t)e * O_DIM + n0, H_DIM,
                       acc, fs);

    const float* bb = b2 + e * O_DIM + n0;
#pragma unroll
    for (int mf = 0; mf < 4; mf++) {
#pragma unroll
        for (int half = 0; half < 2; half++) {
            int lrow = fs.wm * 64 + mf * 16 + g + half * 8;
            if (rt * BM + lrow >= cnt) continue;
            int tkn = stok[lrow];
            float w = sw[lrow];
            float* orow = out + (size_t)tkn * O_DIM + n0;
#pragma unroll
            for (int nf = 0; nf < 4; nf++) {
                int col = fs.wn * 32 + nf * 8 + 2 * t4;
                float v0 = (acc[mf][nf][half * 2 + 0] + __ldg(&bb[col]))     * w;
                float v1 = (acc[mf][nf][half * 2 + 1] + __ldg(&bb[col + 1])) * w;
                atomicAdd(&orow[col], v0);
                atomicAdd(&orow[col + 1], v1);
            }
        }
    }
}

// ---------------- launch ----------------
extern "C" void kernel_launch(void* const* d_in, const int* in_sizes, int n_in,
                              void* d_out, int out_size) {
    const float* x  = (const float*)d_in[0];
    const float* Wg = (const float*)d_in[1];
    const float* W1 = (const float*)d_in[2];
    const float* b1 = (const float*)d_in[3];
    const float* W2 = (const float*)d_in[4];
    const float* b2 = (const float*)d_in[5];
    float* out = (float*)d_out;
    int write_gate = (out_size >= OUT_ELEMS + GATE_ELEMS) ? 1 : 0;

    static int smem_configured = 0;
    if (!smem_configured) {
        cudaFuncSetAttribute(ffn1_mma_kernel,
                             cudaFuncAttributeMaxDynamicSharedMemorySize, SMEM_ALLOC);
        cudaFuncSetAttribute(ffn2_mma_kernel,
                             cudaFuncAttributeMaxDynamicSharedMemorySize, SMEM_ALLOC);
        smem_configured = 1;
    }

    zero_kernel<<<1024, 256>>>(out);
    prep_x_kernel<<<(T_TOK * D_IN / 4 + 255) / 256, 256>>>(x);
    prep_w1t_kernel<<<dim3(H_DIM / 32, D_IN / 64, NEXP), dim3(32, 8)>>>(W1);
    prep_w2t_kernel<<<dim3(O_DIM / 32, H_DIM / 64, NEXP), dim3(32, 8)>>>(W2);
    gate_kernel<<<T_TOK / 8, 256>>>(x, Wg, out + OUT_ELEMS, write_gate);
    scan_kernel<<<1, 32>>>();
    scatter_kernel<<<T_TOK / 256, 256>>>();
    ffn1_mma_kernel<<<dim3(H_DIM / BN, 32, NEXP), 256, SMEM_ALLOC>>>(b1);
    ffn2_mma_kernel<<<dim3(O_DIM / BN, 32, NEXP), 256, SMEM_ALLOC>>>(b2, out);
}

// round 16
// speedup vs baseline: 2.2291x; 1.0159x over previous
#include <cuda_runtime.h>
#include <cuda_bf16.h>
#include <math.h>
#include <stdint.h>

// Problem constants
#define T_TOK   4096
#define D_IN    768
#define NEXP    8
#define H_DIM   3072
#define O_DIM   768
#define OUT_ELEMS  (T_TOK * O_DIM)
#define GATE_ELEMS (T_TOK * NEXP)
#define ROWCAP  8320

// GEMM tiling (mma.sync bf16 m16n8k16)
#define BM 128
#define BN 128
#define BK 32
#define ROWB 80               // bytes per smem row (64 data + 16 pad)
#define KSPLIT2 4             // split-K factor for FFN2
// smem byte offsets within one stage
#define A_HI 0
#define A_LO (BM * ROWB)
#define B_HI (2 * BM * ROWB)
#define B_LO (2 * BM * ROWB + BN * ROWB)
#define STAGE_BYTES (2 * BM * ROWB + 2 * BN * ROWB)   // 40960
#define SMEM_ALLOC (2 * STAGE_BYTES)                  // 81920 (2-stage)

// ---------------- scratch ----------------
__device__ int   g_cnt[NEXP];
__device__ int   g_off[NEXP];
__device__ int   g_tope[T_TOK * 2];
__device__ float g_topw[T_TOK * 2];
__device__ int   g_rowtok[ROWCAP];
__device__ float g_roww[ROWCAP];

__device__ __nv_bfloat16 g_xhi[T_TOK * D_IN];
__device__ __nv_bfloat16 g_xlo[T_TOK * D_IN];
__device__ __nv_bfloat16 g_w1hi[NEXP * H_DIM * D_IN];   // [e][n][k]
__device__ __nv_bfloat16 g_w1lo[NEXP * H_DIM * D_IN];
__device__ __nv_bfloat16 g_w2hi[NEXP * O_DIM * H_DIM];  // [e][n][k]
__device__ __nv_bfloat16 g_w2lo[NEXP * O_DIM * H_DIM];
__device__ __nv_bfloat16 g_hhi[(size_t)ROWCAP * H_DIM];
__device__ __nv_bfloat16 g_hlo[(size_t)ROWCAP * H_DIM];

// ---------------- helpers ----------------
__device__ __forceinline__ float gelu_exact(float v) {
    return 0.5f * v * (1.0f + erff(v * 0.70710678118654752f));
}
__device__ __forceinline__ void split_bf16(float v, __nv_bfloat16& hi, __nv_bfloat16& lo) {
    hi = __float2bfloat16(v);
    lo = __float2bfloat16(v - __bfloat162float(hi));
}
__device__ __forceinline__ void mma_bf16(float* c, const uint32_t* a,
                                         uint32_t b0, uint32_t b1) {
    asm volatile(
        "mma.sync.aligned.m16n8k16.row.col.f32.bf16.bf16.f32 "
        "{%0,%1,%2,%3}, {%4,%5,%6,%7}, {%8,%9}, {%0,%1,%2,%3};"
        : "+f"(c[0]), "+f"(c[1]), "+f"(c[2]), "+f"(c[3])
        : "r"(a[0]), "r"(a[1]), "r"(a[2]), "r"(a[3]), "r"(b0), "r"(b1));
}
__device__ __forceinline__ void ldsm_x4(uint32_t* r, uint32_t saddr) {
    asm volatile(
        "ldmatrix.sync.aligned.m8n8.x4.shared.b16 {%0,%1,%2,%3}, [%4];"
        : "=r"(r[0]), "=r"(r[1]), "=r"(r[2]), "=r"(r[3]) : "r"(saddr));
}
__device__ __forceinline__ void cp16(uint32_t dst, const void* src) {
    asm volatile("cp.async.cg.shared.global [%0], [%1], 16;"
                 :: "r"(dst), "l"(src) : "memory");
}
__device__ __forceinline__ void cp_commit() {
    asm volatile("cp.async.commit_group;" ::: "memory");
}
template <int N>
__device__ __forceinline__ void cp_wait() {
    asm volatile("cp.async.wait_group %0;" :: "n"(N) : "memory");
}

// ---------------- kernel 1: zero output + counts + split x ----------------
__global__ void zero_prepx_kernel(const float* __restrict__ x, float* __restrict__ out) {
    int idx = blockIdx.x * blockDim.x + threadIdx.x;
    // prep x: exactly one float4 per thread (grid sized to T*D/4)
    float4 v = reinterpret_cast<const float4*>(x)[idx];
    __nv_bfloat16 h0, h1, h2, h3, l0, l1, l2, l3;
    split_bf16(v.x, h0, l0); split_bf16(v.y, h1, l1);
    split_bf16(v.z, h2, l2); split_bf16(v.w, h3, l3);
    __nv_bfloat162* ph = reinterpret_cast<__nv_bfloat162*>(&g_xhi[4 * idx]);
    __nv_bfloat162* pl = reinterpret_cast<__nv_bfloat162*>(&g_xlo[4 * idx]);
    ph[0] = __halves2bfloat162(h0, h1); ph[1] = __halves2bfloat162(h2, h3);
    pl[0] = __halves2bfloat162(l0, l1); pl[1] = __halves2bfloat162(l2, l3);
    // zero output (OUT_ELEMS/4 float4s <= grid size)
    const int n4 = OUT_ELEMS / 4;
    if (idx < n4)
        reinterpret_cast<float4*>(out)[idx] = make_float4(0.f, 0.f, 0.f, 0.f);
    if (idx < NEXP) g_cnt[idx] = 0;
}

// ---------------- prep: transpose + split W -> [e][n][k] --------------------
__device__ __forceinline__ void prep_wt_tile(
    const float* __restrict__ W, __nv_bfloat16* __restrict__ Hi,
    __nv_bfloat16* __restrict__ Lo, int n0, int k0, int NLD, int KLD)
{
    __shared__ float tile[32][66];
    int tx = threadIdx.x, ty = threadIdx.y;
    for (int r = ty; r < 64; r += 8)
        tile[tx][r] = W[(size_t)(k0 + r) * NLD + n0 + tx];
    __syncthreads();
    for (int r = ty; r < 32; r += 8) {
        float v0 = tile[r][2 * tx], v1 = tile[r][2 * tx + 1];
        __nv_bfloat16 h0, l0, h1, l1;
        split_bf16(v0, h0, l0); split_bf16(v1, h1, l1);
        size_t o = (size_t)(n0 + r) * KLD + k0 + 2 * tx;
        *reinterpret_cast<__nv_bfloat162*>(&Hi[o]) = __halves2bfloat162(h0, h1);
        *reinterpret_cast<__nv_bfloat162*>(&Lo[o]) = __halves2bfloat162(l0, l1);
    }
}

__global__ void prep_w1t_kernel(const float* __restrict__ W1) {
    int e = blockIdx.z;
    prep_wt_tile(W1 + (size_t)e * D_IN * H_DIM,
                 g_w1hi + (size_t)e * H_DIM * D_IN,
                 g_w1lo + (size_t)e * H_DIM * D_IN,
                 blockIdx.x * 32, blockIdx.y * 64, H_DIM, D_IN);
}

__global__ void prep_w2t_kernel(const float* __restrict__ W2) {
    int e = blockIdx.z;
    prep_wt_tile(W2 + (size_t)e * H_DIM * O_DIM,
                 g_w2hi + (size_t)e * O_DIM * H_DIM,
                 g_w2lo + (size_t)e * O_DIM * H_DIM,
                 blockIdx.x * 32, blockIdx.y * 64, O_DIM, H_DIM);
}

// ---------------- gate (exact fp32) ----------------
__global__ __launch_bounds__(256) void gate_kernel(
    const float* __restrict__ x, const float* __restrict__ Wg,
    float* __restrict__ gate_out, int write_gate)
{
    __shared__ float sWg[D_IN * NEXP];
    for (int i = threadIdx.x; i < D_IN * NEXP; i += blockDim.x) sWg[i] = Wg[i];
    __syncthreads();

    int warp = threadIdx.x >> 5, lane = threadIdx.x & 31;
    int t = blockIdx.x * 8 + warp;
    const float* xr = x + (size_t)t * D_IN;

    float acc[NEXP];
#pragma unroll
    for (int e = 0; e < NEXP; e++) acc[e] = 0.f;
    for (int d = lane; d < D_IN; d += 32) {
        float xv = xr[d];
#pragma unroll
        for (int e = 0; e < NEXP; e++) acc[e] = fmaf(xv, sWg[d * NEXP + e], acc[e]);
    }
#pragma unroll
    for (int o = 16; o > 0; o >>= 1)
#pragma unroll
        for (int e = 0; e < NEXP; e++) acc[e] += __shfl_xor_sync(0xffffffffu, acc[e], o);

    int i0 = 0; float v0 = acc[0];
#pragma unroll
    for (int e = 1; e < NEXP; e++) if (acc[e] > v0) { v0 = acc[e]; i0 = e; }
    int i1 = -1; float v1 = -3.4e38f;
#pragma unroll
    for (int e = 0; e < NEXP; e++) if (e != i0 && acc[e] > v1) { v1 = acc[e]; i1 = e; }

    float ew = expf(v1 - v0);
    float denom = 1.f + ew;
    float w0 = 1.f / denom, w1 = ew / denom;

    if (write_gate && lane < NEXP)
        gate_out[t * NEXP + lane] = (lane == i0) ? w0 : ((lane == i1) ? w1 : 0.f);
    if (lane == 0) {
        g_tope[2 * t] = i0;     g_topw[2 * t] = w0;
        g_tope[2 * t + 1] = i1; g_topw[2 * t + 1] = w1;
        atomicAdd(&g_cnt[i0], 1);
        atomicAdd(&g_cnt[i1], 1);
    }
}

// ---------------- scan + scatter fused (single block) ----------------
__global__ __launch_bounds__(256) void scan_scatter_kernel() {
    __shared__ int scur[NEXP];
    if (threadIdx.x == 0) {
        int off = 0;
        for (int e = 0; e < NEXP; e++) {
            g_off[e] = off; scur[e] = off; off += g_cnt[e];
        }
    }
    __syncthreads();
    for (int t = threadIdx.x; t < T_TOK; t += 256) {
#pragma unroll
        for (int k = 0; k < 2; k++) {
            int e = g_tope[2 * t + k];
            float w = g_topw[2 * t + k];
            int pos = atomicAdd(&scur[e], 1);
            g_rowtok[pos] = t;
            g_roww[pos] = w;
        }
    }
}

// ================= FFN GEMM core (mma.sync bf16, 3-term split) =============
// CTA 128x128, 256 thr, warp grid 2(m) x 4(n), warp tile 64x32.
// 2-stage cp.async pipeline; ldmatrix.x4 fragment loads; 80B padded stride.

struct FragState { int wm, wn; };

__device__ __forceinline__ void gemm_tile_mainloop(
    char* smem, int tid, int KTOT,
    const __nv_bfloat16* Ahi_base, const __nv_bfloat16* Alo_base,
    const int* stokRow,             // nullptr -> contiguous rows from arow0
    size_t arow0, int a_ld,
    const __nv_bfloat16* Bhi_base, const __nv_bfloat16* Blo_base,
    size_t brow0, int b_ld,
    float acc[4][4][4], const FragState& fs)
{
    const int rA0 = tid >> 2, segA = (tid & 3) * 16;
    const int rA1 = rA0 + 64;
    size_t ga0 = (stokRow ? (size_t)stokRow[rA0] : (arow0 + rA0)) * a_ld;
    size_t ga1 = (stokRow ? (size_t)stokRow[rA1] : (arow0 + rA1)) * a_ld;
    size_t gb0 = (brow0 + rA0) * b_ld;
    size_t gb1 = (brow0 + rA1) * b_ld;

    const uint32_t s_base = (uint32_t)__cvta_generic_to_shared(smem);
    const uint32_t dA0 = s_base + A_HI + rA0 * ROWB + segA;
    const uint32_t dA1 = s_base + A_HI + rA1 * ROWB + segA;
    const uint32_t dB0 = s_base + B_HI + rA0 * ROWB + segA;
    const uint32_t dB1 = s_base + B_HI + rA1 * ROWB + segA;

    const int lane = tid & 31;
    const int quad = lane >> 3, lr = lane & 7;
    const uint32_t laneA = ((quad & 1) * 8 + lr) * ROWB + (quad >> 1) * 16;
    const uint32_t laneB = ((quad >> 1) * 8 + lr) * ROWB + (quad & 1) * 16;
    const uint32_t aBase0 = s_base + A_HI + (fs.wm * 64) * ROWB + laneA;
    const uint32_t bBase0 = s_base + B_HI + (fs.wn * 32) * ROWB + laneB;

    const int NCH = KTOT / BK;

    auto fill = [&](int st, int k0) {
        uint32_t so = (uint32_t)(st * STAGE_BYTES);
        size_t o0 = (ga0 + k0) * 2 + segA, o1 = (ga1 + k0) * 2 + segA;
        cp16(dA0 + so,                (const char*)Ahi_base + o0);
        cp16(dA1 + so,                (const char*)Ahi_base + o1);
        cp16(dA0 + so + (A_LO - A_HI), (const char*)Alo_base + o0);
        cp16(dA1 + so + (A_LO - A_HI), (const char*)Alo_base + o1);
        size_t p0 = (gb0 + k0) * 2 + segA, p1 = (gb1 + k0) * 2 + segA;
        cp16(dB0 + so,                (const char*)Bhi_base + p0);
        cp16(dB1 + so,                (const char*)Bhi_base + p1);
        cp16(dB0 + so + (B_LO - B_HI), (const char*)Blo_base + p0);
        cp16(dB1 + so + (B_LO - B_HI), (const char*)Blo_base + p1);
    };

    fill(0, 0);
    cp_commit();

    for (int ic = 0; ic < NCH; ic++) {
        if (ic + 1 < NCH) {
            fill((ic + 1) & 1, (ic + 1) * BK);
            cp_commit();
            cp_wait<1>();
        } else {
            cp_wait<0>();
        }
        __syncthreads();

        const uint32_t so = (uint32_t)((ic & 1) * STAGE_BYTES);
        const uint32_t aBase = aBase0 + so;
        const uint32_t bBase = bBase0 + so;

#pragma unroll
        for (int ks = 0; ks < 2; ks++) {
            uint32_t ah[4][4], al[4][4];
#pragma unroll
            for (int mf = 0; mf < 4; mf++) {
                uint32_t aaddr = aBase + mf * 16 * ROWB + ks * 32;
                ldsm_x4(ah[mf], aaddr);
                ldsm_x4(al[mf], aaddr + (A_LO - A_HI));
            }
#pragma unroll
            for (int pair = 0; pair < 2; pair++) {
                uint32_t baddr = bBase + pair * 16 * ROWB + ks * 32;
                uint32_t bh4[4], bl4[4];
                ldsm_x4(bh4, baddr);
                ldsm_x4(bl4, baddr + (B_LO - B_HI));
#pragma unroll
                for (int mf = 0; mf < 4; mf++) {
                    mma_bf16(acc[mf][2 * pair],     ah[mf], bh4[0], bh4[1]);
                    mma_bf16(acc[mf][2 * pair],     ah[mf], bl4[0], bl4[1]);
                    mma_bf16(acc[mf][2 * pair],     al[mf], bh4[0], bh4[1]);
                    mma_bf16(acc[mf][2 * pair + 1], ah[mf], bh4[2], bh4[3]);
                    mma_bf16(acc[mf][2 * pair + 1], ah[mf], bl4[2], bl4[3]);
                    mma_bf16(acc[mf][2 * pair + 1], al[mf], bh4[2], bh4[3]);
                }
            }
        }
        __syncthreads();
    }
}

// ---------------- FFN1: h = gelu(x @ W1 + b1) -------------------------------
__global__ __launch_bounds__(256, 2) void ffn1_mma_kernel(const float* __restrict__ b1)
{
    const int e = blockIdx.z;
    const int cnt = g_cnt[e];
    const int rt = blockIdx.y;
    if (rt * BM >= cnt) return;
    const int m0 = g_off[e] + rt * BM;
    const int n0 = blockIdx.x * BN;

    extern __shared__ __align__(16) char smem[];
    __shared__ int stok[BM];

    const int tid = threadIdx.x;
    const int wid = tid >> 5, lane = tid & 31;
    FragState fs;
    fs.wm = wid & 1; fs.wn = wid >> 1;
    const int g = lane >> 2, t4 = lane & 3;

    if (tid < BM) {
        int slot = rt * BM + tid;
        stok[tid] = (slot < cnt) ? g_rowtok[m0 + tid] : g_rowtok[m0];
    }
    __syncthreads();

    float acc[4][4][4];
#pragma unroll
    for (int a = 0; a < 4; a++)
#pragma unroll
        for (int b = 0; b < 4; b++)
#pragma unroll
            for (int c = 0; c < 4; c++) acc[a][b][c] = 0.f;

    gemm_tile_mainloop(smem, tid, D_IN,
                       g_xhi, g_xlo, stok, 0, D_IN,
                       g_w1hi, g_w1lo, (size_t)e * H_DIM + n0, D_IN,
                       acc, fs);

    const float* bb = b1 + e * H_DIM + n0;
#pragma unroll
    for (int mf = 0; mf < 4; mf++) {
#pragma unroll
        for (int half = 0; half < 2; half++) {
            int lrow = fs.wm * 64 + mf * 16 + g + half * 8;
            if (rt * BM + lrow >= cnt) continue;
            size_t gr = m0 + lrow;
#pragma unroll
            for (int nf = 0; nf < 4; nf++) {
                int col = fs.wn * 32 + nf * 8 + 2 * t4;
                float v0 = acc[mf][nf][half * 2 + 0] + __ldg(&bb[col]);
                float v1 = acc[mf][nf][half * 2 + 1] + __ldg(&bb[col + 1]);
                v0 = gelu_exact(v0); v1 = gelu_exact(v1);
                __nv_bfloat16 h0, l0, h1, l1;
                split_bf16(v0, h0, l0); split_bf16(v1, h1, l1);
                size_t o = gr * H_DIM + n0 + col;
                *reinterpret_cast<__nv_bfloat162*>(&g_hhi[o]) = __halves2bfloat162(h0, h1);
                *reinterpret_cast<__nv_bfloat162*>(&g_hlo[o]) = __halves2bfloat162(l0, l1);
            }
        }
    }
}

// ---------------- FFN2: out += w * (h @ W2 + b2), split-K ------------------
__global__ __launch_bounds__(256, 2) void ffn2_mma_kernel(
    const float* __restrict__ b2, float* __restrict__ out)
{
    const int e = blockIdx.z;
    const int cnt = g_cnt[e];
    const int rt = blockIdx.y;
    if (rt * BM >= cnt) return;
    const int m0 = g_off[e] + rt * BM;
    const int kspl = blockIdx.x / (O_DIM / BN);        // 0..KSPLIT2-1
    const int n0 = (blockIdx.x % (O_DIM / BN)) * BN;
    const int kbase = kspl * (H_DIM / KSPLIT2);

    extern __shared__ __align__(16) char smem[];
    __shared__ int   stok[BM];
    __shared__ float sw[BM];

    const int tid = threadIdx.x;
    const int wid = tid >> 5, lane = tid & 31;
    FragState fs;
    fs.wm = wid & 1; fs.wn = wid >> 1;
    const int g = lane >> 2, t4 = lane & 3;

    if (tid < BM) {
        int slot = rt * BM + tid;
        stok[tid] = (slot < cnt) ? g_rowtok[m0 + tid] : 0;
        sw[tid]   = (slot < cnt) ? g_roww[m0 + tid]  : 0.f;
    }
    __syncthreads();

    float acc[4][4][4];
#pragma unroll
    for (int a = 0; a < 4; a++)
#pragma unroll
        for (int b = 0; b < 4; b++)
#pragma unroll
            for (int c = 0; c < 4; c++) acc[a][b][c] = 0.f;

    gemm_tile_mainloop(smem, tid, H_DIM / KSPLIT2,
                       g_hhi + kbase, g_hlo + kbase, nullptr, (size_t)m0, H_DIM,
                       g_w2hi + kbase, g_w2lo + kbase,
                       (size_t)e * O_DIM + n0, H_DIM,
                       acc, fs);

    const float* bb = b2 + e * O_DIM + n0;
    const float bias_scale = (kspl == 0) ? 1.f : 0.f;
#pragma unroll
    for (int mf = 0; mf < 4; mf++) {
#pragma unroll
        for (int half = 0; half < 2; half++) {
            int lrow = fs.wm * 64 + mf * 16 + g + half * 8;
            if (rt * BM + lrow >= cnt) continue;
            int tkn = stok[lrow];
            float w = sw[lrow];
            float* orow = out + (size_t)tkn * O_DIM + n0;
#pragma unroll
            for (int nf = 0; nf < 4; nf++) {
                int col = fs.wn * 32 + nf * 8 + 2 * t4;
                float v0 = (acc[mf][nf][half * 2 + 0] + bias_scale * __ldg(&bb[col]))     * w;
                float v1 = (acc[mf][nf][half * 2 + 1] + bias_scale * __ldg(&bb[col + 1])) * w;
                atomicAdd(&orow[col], v0);
                atomicAdd(&orow[col + 1], v1);
            }
        }
    }
}

// ---------------- launch ----------------
extern "C" void kernel_launch(void* const* d_in, const int* in_sizes, int n_in,
                              void* d_out, int out_size) {
    const float* x  = (const float*)d_in[0];
    const float* Wg = (const float*)d_in[1];
    const float* W1 = (const float*)d_in[2];
    const float* b1 = (const float*)d_in[3];
    const float* W2 = (const float*)d_in[4];
    const float* b2 = (const float*)d_in[5];
    float* out = (float*)d_out;
    int write_gate = (out_size >= OUT_ELEMS + GATE_ELEMS) ? 1 : 0;

    static int smem_configured = 0;
    if (!smem_configured) {
        cudaFuncSetAttribute(ffn1_mma_kernel,
                             cudaFuncAttributeMaxDynamicSharedMemorySize, SMEM_ALLOC);
        cudaFuncSetAttribute(ffn2_mma_kernel,
                             cudaFuncAttributeMaxDynamicSharedMemorySize, SMEM_ALLOC);
        smem_configured = 1;
    }

    // launch order arranged so ffn1_mma_kernel is launch #6 (ncu -s 5 -c 1)
    zero_prepx_kernel<<<T_TOK * D_IN / 4 / 256, 256>>>(x, out);          // 1
    prep_w1t_kernel<<<dim3(H_DIM / 32, D_IN / 64, NEXP), dim3(32, 8)>>>(W1);  // 2
    prep_w2t_kernel<<<dim3(O_DIM / 32, H_DIM / 64, NEXP), dim3(32, 8)>>>(W2); // 3
    gate_kernel<<<T_TOK / 8, 256>>>(x, Wg, out + OUT_ELEMS, write_gate); // 4
    scan_scatter_kernel<<<1, 256>>>();                                   // 5
    ffn1_mma_kernel<<<dim3(H_DIM / BN, 32, NEXP), 256, SMEM_ALLOC>>>(b1);      // 6
    ffn2_mma_kernel<<<dim3((O_DIM / BN) * KSPLIT2, 32, NEXP), 256, SMEM_ALLOC>>>(b2, out); // 7
}